// round 1
// baseline (speedup 1.0000x reference)
#include <cuda_runtime.h>

#define HDIM 128
#define RBLOCKS 256

// ---------------- device scratch (static, no allocation) ----------------
__device__ float d_G0[HDIM];                 // x_graph @ W0[0:256] + b0
__device__ float d_Qm[1000 * HDIM];          // x_m @ W0[256:384] + G0
__device__ float d_Pj[5000 * HDIM];          // x_job @ W0[384:512]
__device__ float d_scores[200000];
__device__ float d_bMax[RBLOCKS];
__device__ int   d_bArg[RBLOCKS];
__device__ float d_gMax;
__device__ int   d_gArg;
__device__ float d_pSumE[RBLOCKS];
__device__ float d_pSumS[RBLOCKS];

// ---------------- k0: g0[k] = b0[k] + sum_c x_graph[c] * W0[c,k] ----------------
__global__ void g0_kernel(const float* __restrict__ xg,
                          const float* __restrict__ W0,
                          const float* __restrict__ b0) {
    int k = threadIdx.x;              // 0..127
    __shared__ float xs[2 * HDIM];
    xs[k] = xg[k];
    xs[k + HDIM] = xg[k + HDIM];
    __syncthreads();
    float acc = b0[k];
    #pragma unroll 8
    for (int c = 0; c < 2 * HDIM; c++)
        acc = fmaf(xs[c], W0[c * HDIM + k], acc);
    d_G0[k] = acc;
}

// ---------------- k1: Out[r,:] = X[r,:] @ Wp (+ G0 if mode==0) ----------------
// mode 0: Out = d_Qm (adds d_G0);  mode 1: Out = d_Pj
__global__ void pre_kernel(const float* __restrict__ X,
                           const float* __restrict__ Wp,
                           int rows, int mode) {
    extern __shared__ float sm[];
    float* Ws = sm;            // 128x128
    float* Xs = sm + 16384;    // 32x128
    int tid = threadIdx.x;

    {   // load Wp to shared (coalesced float4)
        const float4* Wg = (const float4*)Wp;
        float4* Ws4 = (float4*)Ws;
        for (int i = tid; i < 4096; i += 256) Ws4[i] = Wg[i];
    }
    __syncthreads();

    int og = tid >> 5;        // 0..7  (op-group / warp)
    int cg = tid & 31;        // 0..31 (col-group of 4)
    float addv[4];
    #pragma unroll
    for (int u = 0; u < 4; u++)
        addv[u] = (mode == 0) ? d_G0[cg * 4 + u] : 0.0f;

    float* Out = (mode == 0) ? d_Qm : d_Pj;

    int ntiles = (rows + 31) >> 5;
    for (int tile = blockIdx.x; tile < ntiles; tile += gridDim.x) {
        int base = tile << 5;
        // stage X tile
        for (int s = tid; s < 1024; s += 256) {
            int r = s >> 5, c4 = (s & 31) << 2;
            float4 v = make_float4(0.f, 0.f, 0.f, 0.f);
            if (base + r < rows)
                v = *(const float4*)&X[(base + r) * HDIM + c4];
            *(float4*)&Xs[r * HDIM + c4] = v;
        }
        __syncthreads();

        float acc[4][4];
        #pragma unroll
        for (int o = 0; o < 4; o++)
            #pragma unroll
            for (int u = 0; u < 4; u++) acc[o][u] = 0.0f;

        #pragma unroll 4
        for (int c = 0; c < HDIM; c += 4) {
            float4 a[4];
            #pragma unroll
            for (int o = 0; o < 4; o++)
                a[o] = *(float4*)&Xs[(og * 4 + o) * HDIM + c];
            #pragma unroll
            for (int u = 0; u < 4; u++) {
                float4 w = *(float4*)&Ws[(c + u) * HDIM + cg * 4];
                #pragma unroll
                for (int o = 0; o < 4; o++) {
                    float av = (&a[o].x)[u];
                    acc[o][0] = fmaf(av, w.x, acc[o][0]);
                    acc[o][1] = fmaf(av, w.y, acc[o][1]);
                    acc[o][2] = fmaf(av, w.z, acc[o][2]);
                    acc[o][3] = fmaf(av, w.w, acc[o][3]);
                }
            }
        }
        #pragma unroll
        for (int o = 0; o < 4; o++) {
            int r = base + og * 4 + o;
            if (r < rows) {
                float4 v;
                v.x = acc[o][0] + addv[0];
                v.y = acc[o][1] + addv[1];
                v.z = acc[o][2] + addv[2];
                v.w = acc[o][3] + addv[3];
                *(float4*)&Out[r * HDIM + cg * 4] = v;
            }
        }
        __syncthreads();
    }
}

// ---------------- k2: main scorer ----------------
// h0 = relu(Qm[m] + Pj[j]); h1 = relu(h0 @ W1 + b1); score = h1 . W2 + b2
__global__ void main_kernel(const int* __restrict__ m_ids,
                            const int* __restrict__ job_idx,
                            const float* __restrict__ W1,
                            const float* __restrict__ b1,
                            const float* __restrict__ W2,
                            const float* __restrict__ b2,
                            int N) {
    extern __shared__ float sm[];
    float* W1s = sm;              // 16384
    float* h0s = sm + 16384;      // 4096
    float* W2s = sm + 20480;      // 128
    float* b1s = sm + 20608;      // 128
    int*   mi  = (int*)(sm + 20736);  // 32
    int*   ji  = mi + 32;             // 32
    int tid = threadIdx.x;

    {
        const float4* Wg = (const float4*)W1;
        float4* Ws4 = (float4*)W1s;
        for (int i = tid; i < 4096; i += 256) Ws4[i] = Wg[i];
    }
    if (tid < HDIM) { W2s[tid] = W2[tid]; b1s[tid] = b1[tid]; }
    __syncthreads();

    int og = tid >> 5;        // warp id, handles ops og*4..og*4+3 of the tile
    int cg = tid & 31;        // lane -> columns cg*4..cg*4+3
    float w2r[4], b1r[4];
    #pragma unroll
    for (int u = 0; u < 4; u++) { w2r[u] = W2s[cg * 4 + u]; b1r[u] = b1s[cg * 4 + u]; }
    float bias2 = b2[0];

    int ntiles = (N + 31) >> 5;
    for (int tile = blockIdx.x; tile < ntiles; tile += gridDim.x) {
        int base = tile << 5;
        if (tid < 32) {
            int op = base + tid;
            mi[tid] = (op < N) ? m_ids[op] : 0;
            ji[tid] = (op < N) ? job_idx[op] : 0;
        }
        __syncthreads();

        // build h0 tile (gather from L2-resident Qm/Pj)
        for (int s = tid; s < 1024; s += 256) {
            int r = s >> 5, c4 = (s & 31) << 2;
            int m = mi[r], j = ji[r];
            float4 q = *(const float4*)&d_Qm[m * HDIM + c4];
            float4 p = *(const float4*)&d_Pj[j * HDIM + c4];
            float4 h;
            h.x = fmaxf(q.x + p.x, 0.f);
            h.y = fmaxf(q.y + p.y, 0.f);
            h.z = fmaxf(q.z + p.z, 0.f);
            h.w = fmaxf(q.w + p.w, 0.f);
            *(float4*)&h0s[r * HDIM + c4] = h;
        }
        __syncthreads();

        float acc[4][4];
        #pragma unroll
        for (int o = 0; o < 4; o++)
            #pragma unroll
            for (int u = 0; u < 4; u++) acc[o][u] = 0.0f;

        #pragma unroll 4
        for (int c = 0; c < HDIM; c += 4) {
            float4 a[4];
            #pragma unroll
            for (int o = 0; o < 4; o++)
                a[o] = *(float4*)&h0s[(og * 4 + o) * HDIM + c];
            #pragma unroll
            for (int u = 0; u < 4; u++) {
                float4 w = *(float4*)&W1s[(c + u) * HDIM + cg * 4];
                #pragma unroll
                for (int o = 0; o < 4; o++) {
                    float av = (&a[o].x)[u];
                    acc[o][0] = fmaf(av, w.x, acc[o][0]);
                    acc[o][1] = fmaf(av, w.y, acc[o][1]);
                    acc[o][2] = fmaf(av, w.z, acc[o][2]);
                    acc[o][3] = fmaf(av, w.w, acc[o][3]);
                }
            }
        }

        // bias + relu + dot W2, warp-reduce -> score
        #pragma unroll
        for (int o = 0; o < 4; o++) {
            float s = 0.f;
            #pragma unroll
            for (int u = 0; u < 4; u++) {
                float h = fmaxf(acc[o][u] + b1r[u], 0.f);
                s = fmaf(h, w2r[u], s);
            }
            #pragma unroll
            for (int off = 16; off > 0; off >>= 1)
                s += __shfl_xor_sync(0xFFFFFFFFu, s, off);
            int op = base + og * 4 + o;
            if (cg == 0 && op < N) d_scores[op] = s + bias2;
        }
        __syncthreads();
    }
}

// ---------------- reductions (deterministic, no atomics) ----------------
__global__ void red_max1(int N) {
    __shared__ float sv[256];
    __shared__ int   si[256];
    float best = -3.402823466e38f;
    int bidx = 0;
    for (int i = blockIdx.x * 256 + threadIdx.x; i < N; i += gridDim.x * 256) {
        float v = d_scores[i];
        if (v > best || (v == best && i < bidx)) { best = v; bidx = i; }
    }
    sv[threadIdx.x] = best; si[threadIdx.x] = bidx;
    __syncthreads();
    for (int s = 128; s > 0; s >>= 1) {
        if (threadIdx.x < s) {
            float v = sv[threadIdx.x + s]; int ix = si[threadIdx.x + s];
            if (v > sv[threadIdx.x] || (v == sv[threadIdx.x] && ix < si[threadIdx.x])) {
                sv[threadIdx.x] = v; si[threadIdx.x] = ix;
            }
        }
        __syncthreads();
    }
    if (threadIdx.x == 0) { d_bMax[blockIdx.x] = sv[0]; d_bArg[blockIdx.x] = si[0]; }
}

__global__ void red_max2() {
    __shared__ float sv[256];
    __shared__ int   si[256];
    sv[threadIdx.x] = d_bMax[threadIdx.x];
    si[threadIdx.x] = d_bArg[threadIdx.x];
    __syncthreads();
    for (int s = 128; s > 0; s >>= 1) {
        if (threadIdx.x < s) {
            float v = sv[threadIdx.x + s]; int ix = si[threadIdx.x + s];
            if (v > sv[threadIdx.x] || (v == sv[threadIdx.x] && ix < si[threadIdx.x])) {
                sv[threadIdx.x] = v; si[threadIdx.x] = ix;
            }
        }
        __syncthreads();
    }
    if (threadIdx.x == 0) { d_gMax = sv[0]; d_gArg = si[0]; }
}

__global__ void red_sum1(int N) {
    __shared__ float sE[256];
    __shared__ float sS[256];
    float mx = d_gMax;
    float se = 0.f, ss = 0.f;
    for (int i = blockIdx.x * 256 + threadIdx.x; i < N; i += gridDim.x * 256) {
        float t = d_scores[i] - mx;
        float e = expf(t);
        se += e;
        ss = fmaf(t, e, ss);
    }
    sE[threadIdx.x] = se; sS[threadIdx.x] = ss;
    __syncthreads();
    for (int s = 128; s > 0; s >>= 1) {
        if (threadIdx.x < s) {
            sE[threadIdx.x] += sE[threadIdx.x + s];
            sS[threadIdx.x] += sS[threadIdx.x + s];
        }
        __syncthreads();
    }
    if (threadIdx.x == 0) { d_pSumE[blockIdx.x] = sE[0]; d_pSumS[blockIdx.x] = sS[0]; }
}

__global__ void finalize_kernel(float* __restrict__ out) {
    __shared__ float sE[256];
    __shared__ float sS[256];
    sE[threadIdx.x] = d_pSumE[threadIdx.x];
    sS[threadIdx.x] = d_pSumS[threadIdx.x];
    __syncthreads();
    for (int s = 128; s > 0; s >>= 1) {
        if (threadIdx.x < s) {
            sE[threadIdx.x] += sE[threadIdx.x + s];
            sS[threadIdx.x] += sS[threadIdx.x + s];
        }
        __syncthreads();
    }
    if (threadIdx.x == 0) {
        float Z = sE[0], S = sS[0];
        float mx = d_gMax;
        int arg = d_gArg;
        float logZ = logf(Z);
        float lp = (d_scores[arg] - mx) - logZ;
        out[0] = (float)arg;        // idx
        out[1] = expf(lp);          // probs[idx]
        out[2] = lp;                // logp[idx]
        out[3] = logZ - S / Z;      // entropy
    }
}

// ---------------- launch ----------------
extern "C" void kernel_launch(void* const* d_in, const int* in_sizes, int n_in,
                              void* d_out, int out_size) {
    const float* xg    = (const float*)d_in[0];
    const float* xm    = (const float*)d_in[1];
    const float* xjob  = (const float*)d_in[2];
    const int*   m_ids = (const int*)d_in[3];
    const int*   jidx  = (const int*)d_in[4];
    const float* W0    = (const float*)d_in[5];
    const float* b0    = (const float*)d_in[6];
    const float* W1    = (const float*)d_in[7];
    const float* b1    = (const float*)d_in[8];
    const float* W2    = (const float*)d_in[9];
    const float* b2    = (const float*)d_in[10];

    int M = in_sizes[1] / HDIM;
    int J = in_sizes[2] / HDIM;
    int N = in_sizes[3];

    const int SMEM_PRE  = (16384 + 4096) * 4;                 // 80 KB
    const int SMEM_MAIN = (16384 + 4096 + 128 + 128) * 4 + 64 * 4;  // ~81.3 KB
    cudaFuncSetAttribute(pre_kernel,  cudaFuncAttributeMaxDynamicSharedMemorySize, SMEM_PRE);
    cudaFuncSetAttribute(main_kernel, cudaFuncAttributeMaxDynamicSharedMemorySize, SMEM_MAIN);

    g0_kernel<<<1, 128>>>(xg, W0, b0);

    int gQm = (M + 31) / 32;
    int gPj = (J + 31) / 32;
    pre_kernel<<<gQm, 256, SMEM_PRE>>>(xm,   W0 + 256 * HDIM, M, 0);
    pre_kernel<<<gPj, 256, SMEM_PRE>>>(xjob, W0 + 384 * HDIM, J, 1);

    main_kernel<<<304, 256, SMEM_MAIN>>>(m_ids, jidx, W1, b1, W2, b2, N);

    red_max1<<<RBLOCKS, 256>>>(N);
    red_max2<<<1, 256>>>();
    red_sum1<<<RBLOCKS, 256>>>(N);
    finalize_kernel<<<1, 256>>>((float*)d_out);
}

// round 2
// speedup vs baseline: 1.0302x; 1.0302x over previous
#include <cuda_runtime.h>

#define HDIM 128
#define RBLOCKS 256

// ---------------- device scratch (static, no allocation) ----------------
__device__ float d_G0[HDIM];
__device__ float d_Qm[1000 * HDIM];
__device__ float d_Pj[5000 * HDIM];
__device__ float d_scores[200000];
__device__ float d_bMax[RBLOCKS];
__device__ int   d_bArg[RBLOCKS];
__device__ float d_gMax;
__device__ int   d_gArg;
__device__ float d_pSumE[RBLOCKS];
__device__ float d_pSumS[RBLOCKS];

// ---------------- f32x2 helpers (Blackwell packed fp32 FMA) ----------------
__device__ __forceinline__ unsigned long long fma_f32x2(unsigned long long a,
                                                        unsigned long long b,
                                                        unsigned long long c) {
    unsigned long long d;
    asm("fma.rn.f32x2 %0, %1, %2, %3;" : "=l"(d) : "l"(a), "l"(b), "l"(c));
    return d;
}
__device__ __forceinline__ unsigned long long pack_dup(float v) {
    unsigned long long d;
    unsigned int r = __float_as_uint(v);
    asm("mov.b64 %0, {%1, %2};" : "=l"(d) : "r"(r), "r"(r));
    return d;
}
__device__ __forceinline__ void unpack2(unsigned long long p, float& lo, float& hi) {
    unsigned int a, b;
    asm("mov.b64 {%0, %1}, %2;" : "=r"(a), "=r"(b) : "l"(p));
    lo = __uint_as_float(a);
    hi = __uint_as_float(b);
}

// ---------------- k0: g0[k] = b0[k] + sum_c x_graph[c] * W0[c,k] ----------------
__global__ void g0_kernel(const float* __restrict__ xg,
                          const float* __restrict__ W0,
                          const float* __restrict__ b0) {
    int k = threadIdx.x;
    __shared__ float xs[2 * HDIM];
    xs[k] = xg[k];
    xs[k + HDIM] = xg[k + HDIM];
    __syncthreads();
    float acc = b0[k];
    #pragma unroll 8
    for (int c = 0; c < 2 * HDIM; c++)
        acc = fmaf(xs[c], W0[c * HDIM + k], acc);
    d_G0[k] = acc;
}

// ---------------- k1: Out[r,:] = X[r,:] @ Wp (+ G0 if mode==0) ----------------
__global__ void pre_kernel(const float* __restrict__ X,
                           const float* __restrict__ Wp,
                           int rows, int mode) {
    extern __shared__ float sm[];
    float* Ws = sm;            // 128x128
    float* Xs = sm + 16384;    // 32x128
    int tid = threadIdx.x;

    {
        const float4* Wg = (const float4*)Wp;
        float4* Ws4 = (float4*)Ws;
        for (int i = tid; i < 4096; i += 256) Ws4[i] = Wg[i];
    }
    __syncthreads();

    int og = tid >> 5;
    int cg = tid & 31;
    float addv[4];
    #pragma unroll
    for (int u = 0; u < 4; u++)
        addv[u] = (mode == 0) ? d_G0[cg * 4 + u] : 0.0f;

    float* Out = (mode == 0) ? d_Qm : d_Pj;

    int ntiles = (rows + 31) >> 5;
    for (int tile = blockIdx.x; tile < ntiles; tile += gridDim.x) {
        int base = tile << 5;
        for (int s = tid; s < 1024; s += 256) {
            int r = s >> 5, c4 = (s & 31) << 2;
            float4 v = make_float4(0.f, 0.f, 0.f, 0.f);
            if (base + r < rows)
                v = *(const float4*)&X[(base + r) * HDIM + c4];
            *(float4*)&Xs[r * HDIM + c4] = v;
        }
        __syncthreads();

        float acc[4][4];
        #pragma unroll
        for (int o = 0; o < 4; o++)
            #pragma unroll
            for (int u = 0; u < 4; u++) acc[o][u] = 0.0f;

        #pragma unroll 4
        for (int c = 0; c < HDIM; c += 4) {
            float4 a[4];
            #pragma unroll
            for (int o = 0; o < 4; o++)
                a[o] = *(float4*)&Xs[(og * 4 + o) * HDIM + c];
            #pragma unroll
            for (int u = 0; u < 4; u++) {
                float4 w = *(float4*)&Ws[(c + u) * HDIM + cg * 4];
                #pragma unroll
                for (int o = 0; o < 4; o++) {
                    float av = (&a[o].x)[u];
                    acc[o][0] = fmaf(av, w.x, acc[o][0]);
                    acc[o][1] = fmaf(av, w.y, acc[o][1]);
                    acc[o][2] = fmaf(av, w.z, acc[o][2]);
                    acc[o][3] = fmaf(av, w.w, acc[o][3]);
                }
            }
        }
        #pragma unroll
        for (int o = 0; o < 4; o++) {
            int r = base + og * 4 + o;
            if (r < rows) {
                float4 v;
                v.x = acc[o][0] + addv[0];
                v.y = acc[o][1] + addv[1];
                v.z = acc[o][2] + addv[2];
                v.w = acc[o][3] + addv[3];
                *(float4*)&Out[r * HDIM + cg * 4] = v;
            }
        }
        __syncthreads();
    }
}

// ---------------- k2: main scorer (f32x2 packed FMA, 48-op tiles) ----------------
#define TOPS 48            // ops per tile (12 warps x 4 ops)
#define TTHREADS 384

__global__ void __launch_bounds__(TTHREADS, 2)
main_kernel(const int* __restrict__ m_ids,
            const int* __restrict__ job_idx,
            const float* __restrict__ W1,
            const float* __restrict__ b1,
            const float* __restrict__ W2,
            const float* __restrict__ b2,
            int N) {
    extern __shared__ float sm[];
    float* W1s = sm;                      // 16384
    float* h0s = sm + 16384;              // TOPS*128 = 6144
    float* W2s = sm + 16384 + 6144;       // 128
    float* b1s = W2s + 128;               // 128
    int*   mi  = (int*)(b1s + 128);       // TOPS
    int*   ji  = mi + TOPS;               // TOPS
    int tid = threadIdx.x;

    {
        const float4* Wg = (const float4*)W1;
        float4* Ws4 = (float4*)W1s;
        for (int i = tid; i < 4096; i += TTHREADS) Ws4[i] = Wg[i];
    }
    if (tid < HDIM) { W2s[tid] = W2[tid]; b1s[tid] = b1[tid]; }
    __syncthreads();

    int og = tid >> 5;        // warp 0..11, ops og*4..og*4+3
    int cg = tid & 31;        // lane -> cols cg*4..cg*4+3
    float w2r[4], b1r[4];
    #pragma unroll
    for (int u = 0; u < 4; u++) { w2r[u] = W2s[cg * 4 + u]; b1r[u] = b1s[cg * 4 + u]; }
    float bias2 = b2[0];

    int ntiles = (N + TOPS - 1) / TOPS;
    for (int tile = blockIdx.x; tile < ntiles; tile += gridDim.x) {
        int base = tile * TOPS;
        if (tid < TOPS) {
            int op = base + tid;
            mi[tid] = (op < N) ? m_ids[op] : 0;
            ji[tid] = (op < N) ? job_idx[op] : 0;
        }
        __syncthreads();

        // build h0 tile (gather from L2/L1-resident Qm/Pj)
        for (int s = tid; s < TOPS * 32; s += TTHREADS) {
            int r = s >> 5, c4 = (s & 31) << 2;
            int m = mi[r], j = ji[r];
            float4 q = *(const float4*)&d_Qm[m * HDIM + c4];
            float4 p = *(const float4*)&d_Pj[j * HDIM + c4];
            float4 h;
            h.x = fmaxf(q.x + p.x, 0.f);
            h.y = fmaxf(q.y + p.y, 0.f);
            h.z = fmaxf(q.z + p.z, 0.f);
            h.w = fmaxf(q.w + p.w, 0.f);
            *(float4*)&h0s[r * HDIM + c4] = h;
        }
        __syncthreads();

        // acc2[o][p]: packed fp32 pair = cols (cg*4+2p, cg*4+2p+1)
        unsigned long long acc2[4][2];
        #pragma unroll
        for (int o = 0; o < 4; o++) { acc2[o][0] = 0ull; acc2[o][1] = 0ull; }

        const float* h0base = &h0s[(og * 4) * HDIM];
        const float* w1base = &W1s[cg * 4];

        #pragma unroll 4
        for (int c = 0; c < HDIM; c += 4) {
            float4 a[4];
            #pragma unroll
            for (int o = 0; o < 4; o++)
                a[o] = *(const float4*)&h0base[o * HDIM + c];   // warp-broadcast LDS
            #pragma unroll
            for (int u = 0; u < 4; u++) {
                ulonglong2 w = *(const ulonglong2*)&w1base[(c + u) * HDIM];
                #pragma unroll
                for (int o = 0; o < 4; o++) {
                    unsigned long long avp = pack_dup((&a[o].x)[u]);
                    acc2[o][0] = fma_f32x2(avp, w.x, acc2[o][0]);
                    acc2[o][1] = fma_f32x2(avp, w.y, acc2[o][1]);
                }
            }
        }

        // bias + relu + dot W2, warp-reduce -> score
        #pragma unroll
        for (int o = 0; o < 4; o++) {
            float h0v, h1v, h2v, h3v;
            unpack2(acc2[o][0], h0v, h1v);
            unpack2(acc2[o][1], h2v, h3v);
            float s = 0.f;
            s = fmaf(fmaxf(h0v + b1r[0], 0.f), w2r[0], s);
            s = fmaf(fmaxf(h1v + b1r[1], 0.f), w2r[1], s);
            s = fmaf(fmaxf(h2v + b1r[2], 0.f), w2r[2], s);
            s = fmaf(fmaxf(h3v + b1r[3], 0.f), w2r[3], s);
            #pragma unroll
            for (int off = 16; off > 0; off >>= 1)
                s += __shfl_xor_sync(0xFFFFFFFFu, s, off);
            int op = base + og * 4 + o;
            if (cg == 0 && op < N) d_scores[op] = s + bias2;
        }
        __syncthreads();
    }
}

// ---------------- reductions (deterministic, no atomics) ----------------
__global__ void red_max1(int N) {
    __shared__ float sv[256];
    __shared__ int   si[256];
    float best = -3.402823466e38f;
    int bidx = 0;
    for (int i = blockIdx.x * 256 + threadIdx.x; i < N; i += gridDim.x * 256) {
        float v = d_scores[i];
        if (v > best || (v == best && i < bidx)) { best = v; bidx = i; }
    }
    sv[threadIdx.x] = best; si[threadIdx.x] = bidx;
    __syncthreads();
    for (int s = 128; s > 0; s >>= 1) {
        if (threadIdx.x < s) {
            float v = sv[threadIdx.x + s]; int ix = si[threadIdx.x + s];
            if (v > sv[threadIdx.x] || (v == sv[threadIdx.x] && ix < si[threadIdx.x])) {
                sv[threadIdx.x] = v; si[threadIdx.x] = ix;
            }
        }
        __syncthreads();
    }
    if (threadIdx.x == 0) { d_bMax[blockIdx.x] = sv[0]; d_bArg[blockIdx.x] = si[0]; }
}

__global__ void red_max2() {
    __shared__ float sv[256];
    __shared__ int   si[256];
    sv[threadIdx.x] = d_bMax[threadIdx.x];
    si[threadIdx.x] = d_bArg[threadIdx.x];
    __syncthreads();
    for (int s = 128; s > 0; s >>= 1) {
        if (threadIdx.x < s) {
            float v = sv[threadIdx.x + s]; int ix = si[threadIdx.x + s];
            if (v > sv[threadIdx.x] || (v == sv[threadIdx.x] && ix < si[threadIdx.x])) {
                sv[threadIdx.x] = v; si[threadIdx.x] = ix;
            }
        }
        __syncthreads();
    }
    if (threadIdx.x == 0) { d_gMax = sv[0]; d_gArg = si[0]; }
}

__global__ void red_sum1(int N) {
    __shared__ float sE[256];
    __shared__ float sS[256];
    float mx = d_gMax;
    float se = 0.f, ss = 0.f;
    for (int i = blockIdx.x * 256 + threadIdx.x; i < N; i += gridDim.x * 256) {
        float t = d_scores[i] - mx;
        float e = expf(t);
        se += e;
        ss = fmaf(t, e, ss);
    }
    sE[threadIdx.x] = se; sS[threadIdx.x] = ss;
    __syncthreads();
    for (int s = 128; s > 0; s >>= 1) {
        if (threadIdx.x < s) {
            sE[threadIdx.x] += sE[threadIdx.x + s];
            sS[threadIdx.x] += sS[threadIdx.x + s];
        }
        __syncthreads();
    }
    if (threadIdx.x == 0) { d_pSumE[blockIdx.x] = sE[0]; d_pSumS[blockIdx.x] = sS[0]; }
}

__global__ void finalize_kernel(float* __restrict__ out) {
    __shared__ float sE[256];
    __shared__ float sS[256];
    sE[threadIdx.x] = d_pSumE[threadIdx.x];
    sS[threadIdx.x] = d_pSumS[threadIdx.x];
    __syncthreads();
    for (int s = 128; s > 0; s >>= 1) {
        if (threadIdx.x < s) {
            sE[threadIdx.x] += sE[threadIdx.x + s];
            sS[threadIdx.x] += sS[threadIdx.x + s];
        }
        __syncthreads();
    }
    if (threadIdx.x == 0) {
        float Z = sE[0], S = sS[0];
        float mx = d_gMax;
        int arg = d_gArg;
        float logZ = logf(Z);
        float lp = (d_scores[arg] - mx) - logZ;
        out[0] = (float)arg;
        out[1] = expf(lp);
        out[2] = lp;
        out[3] = logZ - S / Z;
    }
}

// ---------------- launch ----------------
extern "C" void kernel_launch(void* const* d_in, const int* in_sizes, int n_in,
                              void* d_out, int out_size) {
    const float* xg    = (const float*)d_in[0];
    const float* xm    = (const float*)d_in[1];
    const float* xjob  = (const float*)d_in[2];
    const int*   m_ids = (const int*)d_in[3];
    const int*   jidx  = (const int*)d_in[4];
    const float* W0    = (const float*)d_in[5];
    const float* b0    = (const float*)d_in[6];
    const float* W1    = (const float*)d_in[7];
    const float* b1    = (const float*)d_in[8];
    const float* W2    = (const float*)d_in[9];
    const float* b2    = (const float*)d_in[10];

    int M = in_sizes[1] / HDIM;
    int J = in_sizes[2] / HDIM;
    int N = in_sizes[3];

    const int SMEM_PRE  = (16384 + 4096) * 4;
    const int SMEM_MAIN = (16384 + TOPS * 128 + 128 + 128) * 4 + 2 * TOPS * 4;
    cudaFuncSetAttribute(pre_kernel,  cudaFuncAttributeMaxDynamicSharedMemorySize, SMEM_PRE);
    cudaFuncSetAttribute(main_kernel, cudaFuncAttributeMaxDynamicSharedMemorySize, SMEM_MAIN);

    g0_kernel<<<1, 128>>>(xg, W0, b0);

    int gQm = (M + 31) / 32;
    int gPj = (J + 31) / 32;
    pre_kernel<<<gQm, 256, SMEM_PRE>>>(xm,   W0 + 256 * HDIM, M, 0);
    pre_kernel<<<gPj, 256, SMEM_PRE>>>(xjob, W0 + 384 * HDIM, J, 1);

    main_kernel<<<296, TTHREADS, SMEM_MAIN>>>(m_ids, jidx, W1, b1, W2, b2, N);

    red_max1<<<RBLOCKS, 256>>>(N);
    red_max2<<<1, 256>>>();
    red_sum1<<<RBLOCKS, 256>>>(N);
    finalize_kernel<<<1, 256>>>((float*)d_out);
}

// round 4
// speedup vs baseline: 1.1276x; 1.0945x over previous
#include <cuda_runtime.h>

#define HDIM 128
#define RBLOCKS 256
#define MAXGRID 512

// ---------------- device scratch (static, no allocation) ----------------
__device__ float d_G0[HDIM];
__device__ float d_Qm[1000 * HDIM];
__device__ float d_Pj[5000 * HDIM];
__device__ float d_scores[200000];
__device__ float d_bMax[MAXGRID];
__device__ int   d_bArg[MAXGRID];
__device__ float d_gMax;
__device__ int   d_gArg;
__device__ float d_pSumE[RBLOCKS];
__device__ float d_pSumS[RBLOCKS];

// ---------------- f32x2 helpers (Blackwell packed fp32 FMA) ----------------
__device__ __forceinline__ unsigned long long fma_f32x2(unsigned long long a,
                                                        unsigned long long b,
                                                        unsigned long long c) {
    unsigned long long d;
    asm("fma.rn.f32x2 %0, %1, %2, %3;" : "=l"(d) : "l"(a), "l"(b), "l"(c));
    return d;
}
__device__ __forceinline__ unsigned long long pack_dup(float v) {
    unsigned long long d;
    unsigned int r = __float_as_uint(v);
    asm("mov.b64 %0, {%1, %2};" : "=l"(d) : "r"(r), "r"(r));
    return d;
}
__device__ __forceinline__ void unpack2(unsigned long long p, float& lo, float& hi) {
    unsigned int a, b;
    asm("mov.b64 {%0, %1}, %2;" : "=r"(a), "=r"(b) : "l"(p));
    lo = __uint_as_float(a);
    hi = __uint_as_float(b);
}

// ---------------- k0 ----------------
__global__ void g0_kernel(const float* __restrict__ xg,
                          const float* __restrict__ W0,
                          const float* __restrict__ b0) {
    int k = threadIdx.x;
    __shared__ float xs[2 * HDIM];
    xs[k] = xg[k];
    xs[k + HDIM] = xg[k + HDIM];
    __syncthreads();
    float acc = b0[k];
    #pragma unroll 8
    for (int c = 0; c < 2 * HDIM; c++)
        acc = fmaf(xs[c], W0[c * HDIM + k], acc);
    d_G0[k] = acc;
}

// ---------------- k1: Out[r,:] = X[r,:] @ Wp (+ G0 if mode==0) ----------------
__global__ void pre_kernel(const float* __restrict__ X,
                           const float* __restrict__ Wp,
                           int rows, int mode) {
    extern __shared__ float sm[];
    float* Ws = sm;            // 128x128
    float* Xs = sm + 16384;    // 32x128
    int tid = threadIdx.x;

    {
        const float4* Wg = (const float4*)Wp;
        float4* Ws4 = (float4*)Ws;
        for (int i = tid; i < 4096; i += 256) Ws4[i] = Wg[i];
    }
    __syncthreads();

    int og = tid >> 5;
    int cg = tid & 31;
    float addv[4];
    #pragma unroll
    for (int u = 0; u < 4; u++)
        addv[u] = (mode == 0) ? d_G0[cg * 4 + u] : 0.0f;

    float* Out = (mode == 0) ? d_Qm : d_Pj;

    int ntiles = (rows + 31) >> 5;
    for (int tile = blockIdx.x; tile < ntiles; tile += gridDim.x) {
        int base = tile << 5;
        for (int s = tid; s < 1024; s += 256) {
            int r = s >> 5, c4 = (s & 31) << 2;
            float4 v = make_float4(0.f, 0.f, 0.f, 0.f);
            if (base + r < rows)
                v = *(const float4*)&X[(base + r) * HDIM + c4];
            *(float4*)&Xs[r * HDIM + c4] = v;
        }
        __syncthreads();

        float acc[4][4];
        #pragma unroll
        for (int o = 0; o < 4; o++)
            #pragma unroll
            for (int u = 0; u < 4; u++) acc[o][u] = 0.0f;

        #pragma unroll 4
        for (int c = 0; c < HDIM; c += 4) {
            float4 a[4];
            #pragma unroll
            for (int o = 0; o < 4; o++)
                a[o] = *(float4*)&Xs[(og * 4 + o) * HDIM + c];
            #pragma unroll
            for (int u = 0; u < 4; u++) {
                float4 w = *(float4*)&Ws[(c + u) * HDIM + cg * 4];
                #pragma unroll
                for (int o = 0; o < 4; o++) {
                    float av = (&a[o].x)[u];
                    acc[o][0] = fmaf(av, w.x, acc[o][0]);
                    acc[o][1] = fmaf(av, w.y, acc[o][1]);
                    acc[o][2] = fmaf(av, w.z, acc[o][2]);
                    acc[o][3] = fmaf(av, w.w, acc[o][3]);
                }
            }
        }
        #pragma unroll
        for (int o = 0; o < 4; o++) {
            int r = base + og * 4 + o;
            if (r < rows) {
                float4 v;
                v.x = acc[o][0] + addv[0];
                v.y = acc[o][1] + addv[1];
                v.z = acc[o][2] + addv[2];
                v.w = acc[o][3] + addv[3];
                *(float4*)&Out[r * HDIM + cg * 4] = v;
            }
        }
        __syncthreads();
    }
}

// ---------------- k2: main scorer (8 ops/thread, f32x2, fused per-CTA max) --------
#define OPW 8              // ops per warp-row group (per thread)
#define TTHREADS 256       // 8 warps
#define TOPS (8 * OPW)     // 64 ops per tile

__global__ void __launch_bounds__(TTHREADS, 2)
main_kernel(const int* __restrict__ m_ids,
            const int* __restrict__ job_idx,
            const float* __restrict__ W1,
            const float* __restrict__ b1,
            const float* __restrict__ W2,
            const float* __restrict__ b2,
            int N) {
    extern __shared__ float sm[];
    float* W1s = sm;                      // 16384
    float* h0s = sm + 16384;              // TOPS*128 = 8192
    float* W2s = h0s + TOPS * HDIM;       // 128
    float* b1s = W2s + 128;               // 128
    int*   mi  = (int*)(b1s + 128);       // TOPS
    int*   ji  = mi + TOPS;               // TOPS
    int tid = threadIdx.x;

    {
        const float4* Wg = (const float4*)W1;
        float4* Ws4 = (float4*)W1s;
        for (int i = tid; i < 4096; i += TTHREADS) Ws4[i] = Wg[i];
    }
    if (tid < HDIM) { W2s[tid] = W2[tid]; b1s[tid] = b1[tid]; }
    __syncthreads();

    int og = tid >> 5;        // warp 0..7, ops og*OPW .. og*OPW+OPW-1
    int cg = tid & 31;        // lane -> cols cg*4..cg*4+3
    float w2r[4], b1r[4];
    #pragma unroll
    for (int u = 0; u < 4; u++) { w2r[u] = W2s[cg * 4 + u]; b1r[u] = b1s[cg * 4 + u]; }
    float bias2 = b2[0];

    float tBest = -3.402823466e38f;
    int   tArg  = 0x7FFFFFFF;

    int ntiles = (N + TOPS - 1) / TOPS;
    for (int tile = blockIdx.x; tile < ntiles; tile += gridDim.x) {
        int base = tile * TOPS;
        if (tid < TOPS) {
            int op = base + tid;
            mi[tid] = (op < N) ? m_ids[op] : 0;
            ji[tid] = (op < N) ? job_idx[op] : 0;
        }
        __syncthreads();

        // build h0 tile (gather from L2/L1-resident Qm/Pj)
        for (int s = tid; s < TOPS * 32; s += TTHREADS) {
            int r = s >> 5, c4 = (s & 31) << 2;
            int m = mi[r], j = ji[r];
            float4 q = *(const float4*)&d_Qm[m * HDIM + c4];
            float4 p = *(const float4*)&d_Pj[j * HDIM + c4];
            float4 h;
            h.x = fmaxf(q.x + p.x, 0.f);
            h.y = fmaxf(q.y + p.y, 0.f);
            h.z = fmaxf(q.z + p.z, 0.f);
            h.w = fmaxf(q.w + p.w, 0.f);
            *(float4*)&h0s[r * HDIM + c4] = h;
        }
        __syncthreads();

        // acc2[o][p]: packed fp32 pair = cols (cg*4+2p, cg*4+2p+1)
        unsigned long long acc2[OPW][2];
        #pragma unroll
        for (int o = 0; o < OPW; o++) { acc2[o][0] = 0ull; acc2[o][1] = 0ull; }

        const float* h0base = &h0s[(og * OPW) * HDIM];
        const float* w1base = &W1s[cg * 4];

        #pragma unroll 2
        for (int c = 0; c < HDIM; c += 4) {
            float4 a[OPW];
            #pragma unroll
            for (int o = 0; o < OPW; o++)
                a[o] = *(const float4*)&h0base[o * HDIM + c];   // warp-broadcast LDS
            #pragma unroll
            for (int u = 0; u < 4; u++) {
                ulonglong2 w = *(const ulonglong2*)&w1base[(c + u) * HDIM];
                #pragma unroll
                for (int o = 0; o < OPW; o++) {
                    unsigned long long avp = pack_dup((&a[o].x)[u]);
                    acc2[o][0] = fma_f32x2(avp, w.x, acc2[o][0]);
                    acc2[o][1] = fma_f32x2(avp, w.y, acc2[o][1]);
                }
            }
        }

        // bias + relu + dot W2, warp-reduce -> score; track running argmax
        #pragma unroll
        for (int o = 0; o < OPW; o++) {
            float h0v, h1v, h2v, h3v;
            unpack2(acc2[o][0], h0v, h1v);
            unpack2(acc2[o][1], h2v, h3v);
            float s = 0.f;
            s = fmaf(fmaxf(h0v + b1r[0], 0.f), w2r[0], s);
            s = fmaf(fmaxf(h1v + b1r[1], 0.f), w2r[1], s);
            s = fmaf(fmaxf(h2v + b1r[2], 0.f), w2r[2], s);
            s = fmaf(fmaxf(h3v + b1r[3], 0.f), w2r[3], s);
            #pragma unroll
            for (int off = 16; off > 0; off >>= 1)
                s += __shfl_xor_sync(0xFFFFFFFFu, s, off);
            s += bias2;
            int op = base + og * OPW + o;
            if (op < N) {
                if (cg == 0) d_scores[op] = s;
                if (s > tBest || (s == tBest && op < tArg)) { tBest = s; tArg = op; }
            }
        }
        __syncthreads();
    }

    // block-reduce (tBest, tArg) -> d_bMax/d_bArg[blockIdx.x]
    float* rv = h0s;                // reuse smem
    int*   ri = (int*)(h0s + TTHREADS);
    rv[tid] = tBest; ri[tid] = tArg;
    __syncthreads();
    for (int s = TTHREADS / 2; s > 0; s >>= 1) {
        if (tid < s) {
            float v = rv[tid + s]; int ix = ri[tid + s];
            if (v > rv[tid] || (v == rv[tid] && ix < ri[tid])) { rv[tid] = v; ri[tid] = ix; }
        }
        __syncthreads();
    }
    if (tid == 0) { d_bMax[blockIdx.x] = rv[0]; d_bArg[blockIdx.x] = ri[0]; }
}

// ---------------- reductions ----------------
__global__ void red_max2(int nparts) {
    __shared__ float sv[256];
    __shared__ int   si[256];
    float best = -3.402823466e38f;
    int bidx = 0x7FFFFFFF;
    for (int i = threadIdx.x; i < nparts; i += 256) {
        float v = d_bMax[i]; int ix = d_bArg[i];
        if (v > best || (v == best && ix < bidx)) { best = v; bidx = ix; }
    }
    sv[threadIdx.x] = best; si[threadIdx.x] = bidx;
    __syncthreads();
    for (int s = 128; s > 0; s >>= 1) {
        if (threadIdx.x < s) {
            float v = sv[threadIdx.x + s]; int ix = si[threadIdx.x + s];
            if (v > sv[threadIdx.x] || (v == sv[threadIdx.x] && ix < si[threadIdx.x])) {
                sv[threadIdx.x] = v; si[threadIdx.x] = ix;
            }
        }
        __syncthreads();
    }
    if (threadIdx.x == 0) { d_gMax = sv[0]; d_gArg = si[0]; }
}

__global__ void red_sum1(int N) {
    __shared__ float sE[256];
    __shared__ float sS[256];
    float mx = d_gMax;
    float se = 0.f, ss = 0.f;
    for (int i = blockIdx.x * 256 + threadIdx.x; i < N; i += gridDim.x * 256) {
        float t = d_scores[i] - mx;
        float e = expf(t);
        se += e;
        ss = fmaf(t, e, ss);
    }
    sE[threadIdx.x] = se; sS[threadIdx.x] = ss;
    __syncthreads();
    for (int s = 128; s > 0; s >>= 1) {
        if (threadIdx.x < s) {
            sE[threadIdx.x] += sE[threadIdx.x + s];
            sS[threadIdx.x] += sS[threadIdx.x + s];
        }
        __syncthreads();
    }
    if (threadIdx.x == 0) { d_pSumE[blockIdx.x] = sE[0]; d_pSumS[blockIdx.x] = sS[0]; }
}

__global__ void finalize_kernel(float* __restrict__ out) {
    __shared__ float sE[256];
    __shared__ float sS[256];
    sE[threadIdx.x] = d_pSumE[threadIdx.x];
    sS[threadIdx.x] = d_pSumS[threadIdx.x];
    __syncthreads();
    for (int s = 128; s > 0; s >>= 1) {
        if (threadIdx.x < s) {
            sE[threadIdx.x] += sE[threadIdx.x + s];
            sS[threadIdx.x] += sS[threadIdx.x + s];
        }
        __syncthreads();
    }
    if (threadIdx.x == 0) {
        float Z = sE[0], S = sS[0];
        float mx = d_gMax;
        int arg = d_gArg;
        float logZ = logf(Z);
        float lp = (d_scores[arg] - mx) - logZ;
        out[0] = (float)arg;
        out[1] = expf(lp);
        out[2] = lp;
        out[3] = logZ - S / Z;
    }
}

// ---------------- launch ----------------
extern "C" void kernel_launch(void* const* d_in, const int* in_sizes, int n_in,
                              void* d_out, int out_size) {
    const float* xg    = (const float*)d_in[0];
    const float* xm    = (const float*)d_in[1];
    const float* xjob  = (const float*)d_in[2];
    const int*   m_ids = (const int*)d_in[3];
    const int*   jidx  = (const int*)d_in[4];
    const float* W0    = (const float*)d_in[5];
    const float* b0    = (const float*)d_in[6];
    const float* W1    = (const float*)d_in[7];
    const float* b1    = (const float*)d_in[8];
    const float* W2    = (const float*)d_in[9];
    const float* b2    = (const float*)d_in[10];

    int M = in_sizes[1] / HDIM;
    int J = in_sizes[2] / HDIM;
    int N = in_sizes[3];

    const int GRID_MAIN = 304;
    const int SMEM_PRE  = (16384 + 4096) * 4;
    const int SMEM_MAIN = (16384 + TOPS * HDIM + 128 + 128) * 4 + 2 * TOPS * 4;
    cudaFuncSetAttribute(pre_kernel,  cudaFuncAttributeMaxDynamicSharedMemorySize, SMEM_PRE);
    cudaFuncSetAttribute(main_kernel, cudaFuncAttributeMaxDynamicSharedMemorySize, SMEM_MAIN);

    g0_kernel<<<1, 128>>>(xg, W0, b0);

    int gQm = (M + 31) / 32;
    int gPj = (J + 31) / 32;
    pre_kernel<<<gQm, 256, SMEM_PRE>>>(xm,   W0 + 256 * HDIM, M, 0);
    pre_kernel<<<gPj, 256, SMEM_PRE>>>(xjob, W0 + 384 * HDIM, J, 1);

    main_kernel<<<GRID_MAIN, TTHREADS, SMEM_MAIN>>>(m_ids, jidx, W1, b1, W2, b2, N);

    red_max2<<<1, 256>>>(GRID_MAIN);
    red_sum1<<<RBLOCKS, 256>>>(N);
    finalize_kernel<<<1, 256>>>((float*)d_out);
}

// round 6
// speedup vs baseline: 1.3893x; 1.2321x over previous
#include <cuda_runtime.h>
#include <cuda_bf16.h>
#include <cstdint>

#define HDIM 128
#define RBLOCKS 256
#define MAXGRID 512
#define CANDCAP 1024

// ---------------- device scratch (static, no allocation) ----------------
__device__ float d_G0[HDIM];
__device__ float d_Qm[1000 * HDIM];
__device__ float d_Pj[5000 * HDIM];
__device__ float d_scores[200000];
__device__ float d_bMax[MAXGRID];
__device__ int   d_bArg[MAXGRID];
__device__ float d_gMax;
__device__ int   d_gArg;
__device__ int   d_candCount;
__device__ int   d_candList[CANDCAP];
__device__ int   d_exArg;
__device__ float d_pSumE[RBLOCKS];
__device__ float d_pSumS[RBLOCKS];

// ---------------- k0 ----------------
__global__ void g0_kernel(const float* __restrict__ xg,
                          const float* __restrict__ W0,
                          const float* __restrict__ b0) {
    int k = threadIdx.x;
    __shared__ float xs[2 * HDIM];
    xs[k] = xg[k];
    xs[k + HDIM] = xg[k + HDIM];
    __syncthreads();
    float acc = b0[k];
    #pragma unroll 8
    for (int c = 0; c < 2 * HDIM; c++)
        acc = fmaf(xs[c], W0[c * HDIM + k], acc);
    d_G0[k] = acc;
}

// ---------------- k1: Out[r,:] = X[r,:] @ Wp (+ G0 if mode==0) ----------------
__global__ void pre_kernel(const float* __restrict__ X,
                           const float* __restrict__ Wp,
                           int rows, int mode) {
    extern __shared__ float sm[];
    float* Ws = sm;
    float* Xs = sm + 16384;
    int tid = threadIdx.x;
    {
        const float4* Wg = (const float4*)Wp;
        float4* Ws4 = (float4*)Ws;
        for (int i = tid; i < 4096; i += 256) Ws4[i] = Wg[i];
    }
    __syncthreads();
    int og = tid >> 5, cg = tid & 31;
    float addv[4];
    #pragma unroll
    for (int u = 0; u < 4; u++) addv[u] = (mode == 0) ? d_G0[cg * 4 + u] : 0.0f;
    float* Out = (mode == 0) ? d_Qm : d_Pj;
    int ntiles = (rows + 31) >> 5;
    for (int tile = blockIdx.x; tile < ntiles; tile += gridDim.x) {
        int base = tile << 5;
        for (int s = tid; s < 1024; s += 256) {
            int r = s >> 5, c4 = (s & 31) << 2;
            float4 v = make_float4(0.f, 0.f, 0.f, 0.f);
            if (base + r < rows) v = *(const float4*)&X[(base + r) * HDIM + c4];
            *(float4*)&Xs[r * HDIM + c4] = v;
        }
        __syncthreads();
        float acc[4][4];
        #pragma unroll
        for (int o = 0; o < 4; o++)
            #pragma unroll
            for (int u = 0; u < 4; u++) acc[o][u] = 0.0f;
        #pragma unroll 4
        for (int c = 0; c < HDIM; c += 4) {
            float4 a[4];
            #pragma unroll
            for (int o = 0; o < 4; o++) a[o] = *(float4*)&Xs[(og * 4 + o) * HDIM + c];
            #pragma unroll
            for (int u = 0; u < 4; u++) {
                float4 w = *(float4*)&Ws[(c + u) * HDIM + cg * 4];
                #pragma unroll
                for (int o = 0; o < 4; o++) {
                    float av = (&a[o].x)[u];
                    acc[o][0] = fmaf(av, w.x, acc[o][0]);
                    acc[o][1] = fmaf(av, w.y, acc[o][1]);
                    acc[o][2] = fmaf(av, w.z, acc[o][2]);
                    acc[o][3] = fmaf(av, w.w, acc[o][3]);
                }
            }
        }
        #pragma unroll
        for (int o = 0; o < 4; o++) {
            int r = base + og * 4 + o;
            if (r < rows) {
                float4 v;
                v.x = acc[o][0] + addv[0]; v.y = acc[o][1] + addv[1];
                v.z = acc[o][2] + addv[2]; v.w = acc[o][3] + addv[3];
                *(float4*)&Out[r * HDIM + cg * 4] = v;
            }
        }
        __syncthreads();
    }
}

// ================= HMMA main kernel =================
#define RS 136                     // padded A row stride (elems) = 272B -> conflict-free frags
#define A_HALF_BYTES (128 * RS * 2)   // 34816
#define OFF_AL A_HALF_BYTES
#define OFF_PART (2 * A_HALF_BYTES)   // 69632
#define SMEM_MMA (OFF_PART + 128 * 9 * 4)

__device__ __forceinline__ void mma_bf16(float* d, uint32_t a0, uint32_t a1,
                                         uint32_t a2, uint32_t a3,
                                         uint32_t b0, uint32_t b1) {
    asm volatile(
        "mma.sync.aligned.m16n8k16.row.col.f32.bf16.bf16.f32 "
        "{%0,%1,%2,%3}, {%4,%5,%6,%7}, {%8,%9}, {%0,%1,%2,%3};"
        : "+f"(d[0]), "+f"(d[1]), "+f"(d[2]), "+f"(d[3])
        : "r"(a0), "r"(a1), "r"(a2), "r"(a3), "r"(b0), "r"(b1));
}

__device__ __forceinline__ uint32_t pack_bf16x2(__nv_bfloat16 lo, __nv_bfloat16 hi) {
    __nv_bfloat162 p(lo, hi);
    return *(uint32_t*)&p;
}

__global__ void __launch_bounds__(256, 1)
mma_main(const int* __restrict__ m_ids,
         const int* __restrict__ job_idx,
         const float* __restrict__ W1,
         const float* __restrict__ b1,
         const float* __restrict__ W2,
         const float* __restrict__ b2,
         int N) {
    extern __shared__ char smem[];
    __nv_bfloat16* Ah = (__nv_bfloat16*)smem;
    __nv_bfloat16* Al = (__nv_bfloat16*)(smem + OFF_AL);
    float* part = (float*)(smem + OFF_PART);     // [128][9] padded

    int tid = threadIdx.x;
    int wid = tid >> 5;
    int lane = tid & 31;
    int g = lane >> 2;       // 0..7
    int tig = lane & 3;      // 0..3
    int warpN = wid * 16;

    // ---- load W1 as persistent B fragments (hi/lo bf16) ----
    uint32_t Bh[2][8][2], Bl[2][8][2];
    #pragma unroll
    for (int nt = 0; nt < 2; nt++) {
        int n = warpN + nt * 8 + g;
        #pragma unroll
        for (int kf = 0; kf < 8; kf++) {
            #pragma unroll
            for (int r = 0; r < 2; r++) {
                int k0 = kf * 16 + r * 8 + tig * 2;
                float w0 = W1[k0 * HDIM + n];
                float w1 = W1[(k0 + 1) * HDIM + n];
                __nv_bfloat16 h0 = __float2bfloat16_rn(w0);
                __nv_bfloat16 h1 = __float2bfloat16_rn(w1);
                Bh[nt][kf][r] = pack_bf16x2(h0, h1);
                Bl[nt][kf][r] = pack_bf16x2(
                    __float2bfloat16_rn(w0 - __bfloat162float(h0)),
                    __float2bfloat16_rn(w1 - __bfloat162float(h1)));
            }
        }
    }
    float b1v[2][2], w2v[2][2];
    #pragma unroll
    for (int nt = 0; nt < 2; nt++)
        #pragma unroll
        for (int e = 0; e < 2; e++) {
            int n = warpN + nt * 8 + tig * 2 + e;
            b1v[nt][e] = b1[n];
            w2v[nt][e] = W2[n];
        }
    float bias2 = b2[0];

    float tBest = -3.402823466e38f;
    int   tArg  = 0x7FFFFFFF;

    int ntiles = (N + 127) >> 7;
    for (int tile = blockIdx.x; tile < ntiles; tile += gridDim.x) {
        int base = tile << 7;

        // ---- gather: h0 = relu(Qm[m]+Pj[j]) -> bf16 hi/lo in padded SMEM ----
        {
            int row = tid >> 1;
            int half = tid & 1;
            int op = base + row;
            bool valid = (op < N);
            int m = valid ? m_ids[op] : 0;
            int j = valid ? job_idx[op] : 0;
            const float4* q4 = (const float4*)&d_Qm[m * HDIM + half * 64];
            const float4* p4 = (const float4*)&d_Pj[j * HDIM + half * 64];
            int ebase = row * RS + half * 64;
            #pragma unroll 4
            for (int it = 0; it < 16; it++) {
                float4 q = q4[it], p = p4[it];
                float h0 = valid ? fmaxf(q.x + p.x, 0.f) : 0.f;
                float h1 = valid ? fmaxf(q.y + p.y, 0.f) : 0.f;
                float h2 = valid ? fmaxf(q.z + p.z, 0.f) : 0.f;
                float h3 = valid ? fmaxf(q.w + p.w, 0.f) : 0.f;
                __nv_bfloat16 a0 = __float2bfloat16_rn(h0);
                __nv_bfloat16 a1 = __float2bfloat16_rn(h1);
                __nv_bfloat16 a2 = __float2bfloat16_rn(h2);
                __nv_bfloat16 a3 = __float2bfloat16_rn(h3);
                uint2 hv, lv;
                hv.x = pack_bf16x2(a0, a1);
                hv.y = pack_bf16x2(a2, a3);
                lv.x = pack_bf16x2(__float2bfloat16_rn(h0 - __bfloat162float(a0)),
                                   __float2bfloat16_rn(h1 - __bfloat162float(a1)));
                lv.y = pack_bf16x2(__float2bfloat16_rn(h2 - __bfloat162float(a2)),
                                   __float2bfloat16_rn(h3 - __bfloat162float(a3)));
                *(uint2*)&Ah[ebase + it * 4] = hv;
                *(uint2*)&Al[ebase + it * 4] = lv;
            }
        }
        __syncthreads();

        // ---- MMA: acc[mt][nt] += Ah*Bh + Ah*Bl + Al*Bh ----
        float acc[8][2][4];
        #pragma unroll
        for (int mt = 0; mt < 8; mt++)
            #pragma unroll
            for (int nt = 0; nt < 2; nt++)
                #pragma unroll
                for (int e = 0; e < 4; e++) acc[mt][nt][e] = 0.f;

        #pragma unroll
        for (int kf = 0; kf < 8; kf++) {
            #pragma unroll
            for (int mt = 0; mt < 8; mt++) {
                int eb = (mt * 16 + g) * RS + kf * 16 + tig * 2;
                uint32_t a0 = *(const uint32_t*)&Ah[eb];
                uint32_t a1 = *(const uint32_t*)&Ah[eb + 8 * RS];
                uint32_t a2 = *(const uint32_t*)&Ah[eb + 8];
                uint32_t a3 = *(const uint32_t*)&Ah[eb + 8 * RS + 8];
                mma_bf16(acc[mt][0], a0, a1, a2, a3, Bh[0][kf][0], Bh[0][kf][1]);
                mma_bf16(acc[mt][1], a0, a1, a2, a3, Bh[1][kf][0], Bh[1][kf][1]);
                mma_bf16(acc[mt][0], a0, a1, a2, a3, Bl[0][kf][0], Bl[0][kf][1]);
                mma_bf16(acc[mt][1], a0, a1, a2, a3, Bl[1][kf][0], Bl[1][kf][1]);
                uint32_t l0 = *(const uint32_t*)&Al[eb];
                uint32_t l1 = *(const uint32_t*)&Al[eb + 8 * RS];
                uint32_t l2 = *(const uint32_t*)&Al[eb + 8];
                uint32_t l3 = *(const uint32_t*)&Al[eb + 8 * RS + 8];
                mma_bf16(acc[mt][0], l0, l1, l2, l3, Bh[0][kf][0], Bh[0][kf][1]);
                mma_bf16(acc[mt][1], l0, l1, l2, l3, Bh[1][kf][0], Bh[1][kf][1]);
            }
        }

        // ---- epilogue: relu + W2 partial dot per warp strip ----
        #pragma unroll
        for (int mt = 0; mt < 8; mt++) {
            float p0 = 0.f, p1 = 0.f;
            #pragma unroll
            for (int nt = 0; nt < 2; nt++) {
                p0 = fmaf(fmaxf(acc[mt][nt][0] + b1v[nt][0], 0.f), w2v[nt][0], p0);
                p0 = fmaf(fmaxf(acc[mt][nt][1] + b1v[nt][1], 0.f), w2v[nt][1], p0);
                p1 = fmaf(fmaxf(acc[mt][nt][2] + b1v[nt][0], 0.f), w2v[nt][0], p1);
                p1 = fmaf(fmaxf(acc[mt][nt][3] + b1v[nt][1], 0.f), w2v[nt][1], p1);
            }
            p0 += __shfl_xor_sync(0xFFFFFFFFu, p0, 1);
            p0 += __shfl_xor_sync(0xFFFFFFFFu, p0, 2);
            p1 += __shfl_xor_sync(0xFFFFFFFFu, p1, 1);
            p1 += __shfl_xor_sync(0xFFFFFFFFu, p1, 2);
            if (tig == 0) {
                part[(mt * 16 + g) * 9 + wid] = p0;
                part[(mt * 16 + g + 8) * 9 + wid] = p1;
            }
        }
        __syncthreads();

        if (tid < 128) {
            int row = tid;
            float s = bias2;
            #pragma unroll
            for (int w = 0; w < 8; w++) s += part[row * 9 + w];
            int op = base + row;
            if (op < N) {
                d_scores[op] = s;
                if (s > tBest || (s == tBest && op < tArg)) { tBest = s; tArg = op; }
            }
        }
        __syncthreads();
    }

    // block argmax (approx scores)
    float* rv = (float*)smem;
    int*   ri = (int*)(smem + 1024);
    rv[tid] = tBest; ri[tid] = tArg;
    __syncthreads();
    for (int s = 128; s > 0; s >>= 1) {
        if (tid < s) {
            float v = rv[tid + s]; int ix = ri[tid + s];
            if (v > rv[tid] || (v == rv[tid] && ix < ri[tid])) { rv[tid] = v; ri[tid] = ix; }
        }
        __syncthreads();
    }
    if (tid == 0) { d_bMax[blockIdx.x] = rv[0]; d_bArg[blockIdx.x] = ri[0]; }
}

// ---------------- reductions ----------------
__global__ void red_max2(int nparts) {
    __shared__ float sv[256];
    __shared__ int   si[256];
    float best = -3.402823466e38f;
    int bidx = 0x7FFFFFFF;
    for (int i = threadIdx.x; i < nparts; i += 256) {
        float v = d_bMax[i]; int ix = d_bArg[i];
        if (v > best || (v == best && ix < bidx)) { best = v; bidx = ix; }
    }
    sv[threadIdx.x] = best; si[threadIdx.x] = bidx;
    __syncthreads();
    for (int s = 128; s > 0; s >>= 1) {
        if (threadIdx.x < s) {
            float v = sv[threadIdx.x + s]; int ix = si[threadIdx.x + s];
            if (v > sv[threadIdx.x] || (v == sv[threadIdx.x] && ix < si[threadIdx.x])) {
                sv[threadIdx.x] = v; si[threadIdx.x] = ix;
            }
        }
        __syncthreads();
    }
    if (threadIdx.x == 0) { d_gMax = sv[0]; d_gArg = si[0]; d_candCount = 0; }
}

// find candidates within DELTA of approx max
__global__ void scan_kernel(int N) {
    float thr = d_gMax - 1e-3f;
    for (int i = blockIdx.x * 256 + threadIdx.x; i < N; i += gridDim.x * 256) {
        if (d_scores[i] >= thr) {
            int p = atomicAdd(&d_candCount, 1);
            if (p < CANDCAP) d_candList[p] = i;
        }
    }
}

// exact fp32 rescoring of candidates, deterministic winner
__global__ void refine_kernel(const int* __restrict__ m_ids,
                              const int* __restrict__ job_idx,
                              const float* __restrict__ W1,
                              const float* __restrict__ b1,
                              const float* __restrict__ W2,
                              const float* __restrict__ b2) {
    __shared__ float h0[128];
    __shared__ float red[128];
    __shared__ float bestS;
    __shared__ int bestI;
    int tid = threadIdx.x;
    if (tid == 0) { bestS = -3.402823466e38f; bestI = 0x7FFFFFFF; }
    int cnt = d_candCount;
    if (cnt > CANDCAP) cnt = CANDCAP;
    __syncthreads();
    for (int c = 0; c < cnt; c++) {
        int op = d_candList[c];
        int m = m_ids[op], j = job_idx[op];
        h0[tid] = fmaxf(d_Qm[m * HDIM + tid] + d_Pj[j * HDIM + tid], 0.f);
        __syncthreads();
        float a = b1[tid];
        #pragma unroll 8
        for (int k = 0; k < HDIM; k++)
            a = fmaf(h0[k], W1[k * HDIM + tid], a);
        red[tid] = fmaxf(a, 0.f) * W2[tid];
        __syncthreads();
        for (int s = 64; s > 0; s >>= 1) {
            if (tid < s) red[tid] += red[tid + s];
            __syncthreads();
        }
        if (tid == 0) {
            float s = red[0] + b2[0];
            if (s > bestS || (s == bestS && op < bestI)) { bestS = s; bestI = op; }
        }
        __syncthreads();
    }
    if (tid == 0) d_exArg = bestI;
}

__global__ void red_sum1(int N) {
    __shared__ float sE[256];
    __shared__ float sS[256];
    float mx = d_gMax;
    float se = 0.f, ss = 0.f;
    for (int i = blockIdx.x * 256 + threadIdx.x; i < N; i += gridDim.x * 256) {
        float t = d_scores[i] - mx;
        float e = expf(t);
        se += e;
        ss = fmaf(t, e, ss);
    }
    sE[threadIdx.x] = se; sS[threadIdx.x] = ss;
    __syncthreads();
    for (int s = 128; s > 0; s >>= 1) {
        if (threadIdx.x < s) {
            sE[threadIdx.x] += sE[threadIdx.x + s];
            sS[threadIdx.x] += sS[threadIdx.x + s];
        }
        __syncthreads();
    }
    if (threadIdx.x == 0) { d_pSumE[blockIdx.x] = sE[0]; d_pSumS[blockIdx.x] = sS[0]; }
}

__global__ void finalize_kernel(float* __restrict__ out) {
    __shared__ float sE[256];
    __shared__ float sS[256];
    sE[threadIdx.x] = d_pSumE[threadIdx.x];
    sS[threadIdx.x] = d_pSumS[threadIdx.x];
    __syncthreads();
    for (int s = 128; s > 0; s >>= 1) {
        if (threadIdx.x < s) {
            sE[threadIdx.x] += sE[threadIdx.x + s];
            sS[threadIdx.x] += sS[threadIdx.x + s];
        }
        __syncthreads();
    }
    if (threadIdx.x == 0) {
        float Z = sE[0], S = sS[0];
        float mx = d_gMax;
        int arg = d_exArg;
        float logZ = logf(Z);
        float lp = (d_scores[arg] - mx) - logZ;
        out[0] = (float)arg;
        out[1] = expf(lp);
        out[2] = lp;
        out[3] = logZ - S / Z;
    }
}

// ---------------- launch ----------------
extern "C" void kernel_launch(void* const* d_in, const int* in_sizes, int n_in,
                              void* d_out, int out_size) {
    const float* xg    = (const float*)d_in[0];
    const float* xm    = (const float*)d_in[1];
    const float* xjob  = (const float*)d_in[2];
    const int*   m_ids = (const int*)d_in[3];
    const int*   jidx  = (const int*)d_in[4];
    const float* W0    = (const float*)d_in[5];
    const float* b0    = (const float*)d_in[6];
    const float* W1    = (const float*)d_in[7];
    const float* b1    = (const float*)d_in[8];
    const float* W2    = (const float*)d_in[9];
    const float* b2    = (const float*)d_in[10];

    int M = in_sizes[1] / HDIM;
    int J = in_sizes[2] / HDIM;
    int N = in_sizes[3];

    const int SMEM_PRE = (16384 + 4096) * 4;
    cudaFuncSetAttribute(pre_kernel, cudaFuncAttributeMaxDynamicSharedMemorySize, SMEM_PRE);
    cudaFuncSetAttribute(mma_main,   cudaFuncAttributeMaxDynamicSharedMemorySize, SMEM_MMA);

    g0_kernel<<<1, 128>>>(xg, W0, b0);

    int gQm = (M + 31) / 32;
    int gPj = (J + 31) / 32;
    pre_kernel<<<gQm, 256, SMEM_PRE>>>(xm,   W0 + 256 * HDIM, M, 0);
    pre_kernel<<<gPj, 256, SMEM_PRE>>>(xjob, W0 + 384 * HDIM, J, 1);

    const int GRID_MAIN = 152;
    mma_main<<<GRID_MAIN, 256, SMEM_MMA>>>(m_ids, jidx, W1, b1, W2, b2, N);

    red_max2<<<1, 256>>>(GRID_MAIN);
    scan_kernel<<<128, 256>>>(N);
    refine_kernel<<<1, 128>>>(m_ids, jidx, W1, b1, W2, b2);
    red_sum1<<<RBLOCKS, 256>>>(N);
    finalize_kernel<<<1, 256>>>((float*)d_out);
}

// round 7
// speedup vs baseline: 1.5766x; 1.1348x over previous
#include <cuda_runtime.h>
#include <cuda_bf16.h>
#include <cstdint>

#define HDIM 128
#define RBLOCKS 256
#define MAXGRID 512
#define CANDCAP 1024

// ---------------- device scratch (static, no allocation) ----------------
__device__ float d_G0[HDIM];
__device__ float d_Qm[1000 * HDIM];
__device__ float d_Pj[5000 * HDIM];
__device__ float d_scores[200000];
__device__ float d_bMax[MAXGRID];
__device__ int   d_bArg[MAXGRID];
__device__ float d_gMax;
__device__ int   d_gArg;
__device__ int   d_candCount;
__device__ int   d_candList[CANDCAP];
__device__ int   d_exArg;
__device__ float d_pSumE[RBLOCKS];
__device__ float d_pSumS[RBLOCKS];

// ---------------- k0 ----------------
__global__ void g0_kernel(const float* __restrict__ xg,
                          const float* __restrict__ W0,
                          const float* __restrict__ b0) {
    int k = threadIdx.x;
    __shared__ float xs[2 * HDIM];
    xs[k] = xg[k];
    xs[k + HDIM] = xg[k + HDIM];
    __syncthreads();
    float acc = b0[k];
    #pragma unroll 8
    for (int c = 0; c < 2 * HDIM; c++)
        acc = fmaf(xs[c], W0[c * HDIM + k], acc);
    d_G0[k] = acc;
}

// ---------------- k1: Out[r,:] = X[r,:] @ Wp (+ G0 if mode==0) ----------------
__global__ void pre_kernel(const float* __restrict__ X,
                           const float* __restrict__ Wp,
                           int rows, int mode) {
    extern __shared__ float sm[];
    float* Ws = sm;
    float* Xs = sm + 16384;
    int tid = threadIdx.x;
    {
        const float4* Wg = (const float4*)Wp;
        float4* Ws4 = (float4*)Ws;
        for (int i = tid; i < 4096; i += 256) Ws4[i] = Wg[i];
    }
    __syncthreads();
    int og = tid >> 5, cg = tid & 31;
    float addv[4];
    #pragma unroll
    for (int u = 0; u < 4; u++) addv[u] = (mode == 0) ? d_G0[cg * 4 + u] : 0.0f;
    float* Out = (mode == 0) ? d_Qm : d_Pj;
    int ntiles = (rows + 31) >> 5;
    for (int tile = blockIdx.x; tile < ntiles; tile += gridDim.x) {
        int base = tile << 5;
        for (int s = tid; s < 1024; s += 256) {
            int r = s >> 5, c4 = (s & 31) << 2;
            float4 v = make_float4(0.f, 0.f, 0.f, 0.f);
            if (base + r < rows) v = *(const float4*)&X[(base + r) * HDIM + c4];
            *(float4*)&Xs[r * HDIM + c4] = v;
        }
        __syncthreads();
        float acc[4][4];
        #pragma unroll
        for (int o = 0; o < 4; o++)
            #pragma unroll
            for (int u = 0; u < 4; u++) acc[o][u] = 0.0f;
        #pragma unroll 4
        for (int c = 0; c < HDIM; c += 4) {
            float4 a[4];
            #pragma unroll
            for (int o = 0; o < 4; o++) a[o] = *(float4*)&Xs[(og * 4 + o) * HDIM + c];
            #pragma unroll
            for (int u = 0; u < 4; u++) {
                float4 w = *(float4*)&Ws[(c + u) * HDIM + cg * 4];
                #pragma unroll
                for (int o = 0; o < 4; o++) {
                    float av = (&a[o].x)[u];
                    acc[o][0] = fmaf(av, w.x, acc[o][0]);
                    acc[o][1] = fmaf(av, w.y, acc[o][1]);
                    acc[o][2] = fmaf(av, w.z, acc[o][2]);
                    acc[o][3] = fmaf(av, w.w, acc[o][3]);
                }
            }
        }
        #pragma unroll
        for (int o = 0; o < 4; o++) {
            int r = base + og * 4 + o;
            if (r < rows) {
                float4 v;
                v.x = acc[o][0] + addv[0]; v.y = acc[o][1] + addv[1];
                v.z = acc[o][2] + addv[2]; v.w = acc[o][3] + addv[3];
                *(float4*)&Out[r * HDIM + cg * 4] = v;
            }
        }
        __syncthreads();
    }
}

// ================= HMMA main kernel (64-row tiles, 2 CTAs/SM) =================
#define TROWS 64
#define RS 136                          // padded A row stride (elems), 272B
#define A_HALF_BYTES (TROWS * RS * 2)   // 17408
#define OFF_AL  A_HALF_BYTES
#define OFF_B1S (2 * A_HALF_BYTES)            // 34816
#define OFF_W2S (OFF_B1S + 512)
#define OFF_PART (OFF_W2S + 512)              // 64 rows x 9 floats
#define SMEM_MMA (OFF_PART + TROWS * 9 * 4)

__device__ __forceinline__ void mma_bf16(float* d, uint32_t a0, uint32_t a1,
                                         uint32_t a2, uint32_t a3,
                                         uint32_t b0, uint32_t b1) {
    asm volatile(
        "mma.sync.aligned.m16n8k16.row.col.f32.bf16.bf16.f32 "
        "{%0,%1,%2,%3}, {%4,%5,%6,%7}, {%8,%9}, {%0,%1,%2,%3};"
        : "+f"(d[0]), "+f"(d[1]), "+f"(d[2]), "+f"(d[3])
        : "r"(a0), "r"(a1), "r"(a2), "r"(a3), "r"(b0), "r"(b1));
}

__device__ __forceinline__ void ldsm_x4(uint32_t* r, uint32_t saddr) {
    asm volatile("ldmatrix.sync.aligned.m8n8.x4.shared.b16 {%0,%1,%2,%3}, [%4];"
        : "=r"(r[0]), "=r"(r[1]), "=r"(r[2]), "=r"(r[3]) : "r"(saddr));
}

__device__ __forceinline__ uint32_t smem_u32(const void* p) {
    uint32_t a;
    asm("{ .reg .u64 t; cvta.to.shared.u64 t, %1; cvt.u32.u64 %0, t; }" : "=r"(a) : "l"(p));
    return a;
}

__device__ __forceinline__ uint32_t pack_bf16x2(__nv_bfloat16 lo, __nv_bfloat16 hi) {
    __nv_bfloat162 p(lo, hi);
    return *(uint32_t*)&p;
}

__global__ void __launch_bounds__(256, 2)
mma_main(const int* __restrict__ m_ids,
         const int* __restrict__ job_idx,
         const float* __restrict__ W1,
         const float* __restrict__ b1,
         const float* __restrict__ W2,
         const float* __restrict__ b2,
         int N) {
    extern __shared__ char smem[];
    __nv_bfloat16* Ah = (__nv_bfloat16*)smem;
    float* b1s = (float*)(smem + OFF_B1S);
    float* W2s = (float*)(smem + OFF_W2S);
    float* part = (float*)(smem + OFF_PART);   // [64][9]

    int tid = threadIdx.x;
    int wid = tid >> 5;
    int lane = tid & 31;
    int g = lane >> 2;
    int tig = lane & 3;
    int warpN = wid * 16;

    if (tid < HDIM) { b1s[tid] = b1[tid]; W2s[tid] = W2[tid]; }

    // ---- persistent B fragments (hi/lo bf16), one 16-col N strip per warp ----
    uint32_t Bh[2][8][2], Bl[2][8][2];
    #pragma unroll
    for (int nt = 0; nt < 2; nt++) {
        int n = warpN + nt * 8 + g;
        #pragma unroll
        for (int kf = 0; kf < 8; kf++) {
            #pragma unroll
            for (int r = 0; r < 2; r++) {
                int k0 = kf * 16 + r * 8 + tig * 2;
                float w0 = W1[k0 * HDIM + n];
                float w1 = W1[(k0 + 1) * HDIM + n];
                __nv_bfloat16 h0 = __float2bfloat16_rn(w0);
                __nv_bfloat16 h1 = __float2bfloat16_rn(w1);
                Bh[nt][kf][r] = pack_bf16x2(h0, h1);
                Bl[nt][kf][r] = pack_bf16x2(
                    __float2bfloat16_rn(w0 - __bfloat162float(h0)),
                    __float2bfloat16_rn(w1 - __bfloat162float(h1)));
            }
        }
    }

    // ldmatrix lane offsets: rowOff = lane&15, colOff = (lane>>4)*8
    uint32_t AhS = smem_u32(Ah);
    uint32_t laneByte = (uint32_t)(((lane & 15) * RS + (lane >> 4) * 8) * 2);
    uint32_t AhLane = AhS + laneByte;
    uint32_t AlLane = AhS + OFF_AL + laneByte;

    float tBest = -3.402823466e38f;
    int   tArg  = 0x7FFFFFFF;

    int ntiles = (N + TROWS - 1) / TROWS;
    for (int tile = blockIdx.x; tile < ntiles; tile += gridDim.x) {
        int base = tile * TROWS;

        // ---- gather: h0 = relu(Qm[m]+Pj[j]) -> bf16 hi/lo padded SMEM ----
        {
            int row = tid >> 2;          // 0..63
            int quarter = tid & 3;       // cols quarter*32..+31
            int op = base + row;
            bool valid = (op < N);
            int m = valid ? m_ids[op] : 0;
            int j = valid ? job_idx[op] : 0;
            const float4* q4 = (const float4*)&d_Qm[m * HDIM + quarter * 32];
            const float4* p4 = (const float4*)&d_Pj[j * HDIM + quarter * 32];
            int ebase = row * RS + quarter * 32;
            #pragma unroll
            for (int it = 0; it < 8; it++) {
                float4 q = q4[it], p = p4[it];
                float h0 = valid ? fmaxf(q.x + p.x, 0.f) : 0.f;
                float h1 = valid ? fmaxf(q.y + p.y, 0.f) : 0.f;
                float h2 = valid ? fmaxf(q.z + p.z, 0.f) : 0.f;
                float h3 = valid ? fmaxf(q.w + p.w, 0.f) : 0.f;
                __nv_bfloat16 a0 = __float2bfloat16_rn(h0);
                __nv_bfloat16 a1 = __float2bfloat16_rn(h1);
                __nv_bfloat16 a2 = __float2bfloat16_rn(h2);
                __nv_bfloat16 a3 = __float2bfloat16_rn(h3);
                uint2 hv, lv;
                hv.x = pack_bf16x2(a0, a1);
                hv.y = pack_bf16x2(a2, a3);
                lv.x = pack_bf16x2(__float2bfloat16_rn(h0 - __bfloat162float(a0)),
                                   __float2bfloat16_rn(h1 - __bfloat162float(a1)));
                lv.y = pack_bf16x2(__float2bfloat16_rn(h2 - __bfloat162float(a2)),
                                   __float2bfloat16_rn(h3 - __bfloat162float(a3)));
                *(uint2*)&Ah[ebase + it * 4] = hv;
                *(uint2*)((char*)&Ah[ebase + it * 4] + OFF_AL) = lv;
            }
        }
        __syncthreads();

        // ---- MMA: acc[mt][nt] += Ah*Bh + Ah*Bl + Al*Bh ----
        float acc[4][2][4];
        #pragma unroll
        for (int mt = 0; mt < 4; mt++)
            #pragma unroll
            for (int nt = 0; nt < 2; nt++)
                #pragma unroll
                for (int e = 0; e < 4; e++) acc[mt][nt][e] = 0.f;

        #pragma unroll
        for (int kf = 0; kf < 8; kf++) {
            uint32_t kOff = (uint32_t)(kf * 16 * 2);
            #pragma unroll
            for (int mt = 0; mt < 4; mt++) {
                uint32_t rOff = (uint32_t)(mt * 16 * RS * 2) + kOff;
                uint32_t ah[4], al[4];
                ldsm_x4(ah, AhLane + rOff);
                ldsm_x4(al, AlLane + rOff);
                mma_bf16(acc[mt][0], ah[0], ah[1], ah[2], ah[3], Bh[0][kf][0], Bh[0][kf][1]);
                mma_bf16(acc[mt][1], ah[0], ah[1], ah[2], ah[3], Bh[1][kf][0], Bh[1][kf][1]);
                mma_bf16(acc[mt][0], ah[0], ah[1], ah[2], ah[3], Bl[0][kf][0], Bl[0][kf][1]);
                mma_bf16(acc[mt][1], ah[0], ah[1], ah[2], ah[3], Bl[1][kf][0], Bl[1][kf][1]);
                mma_bf16(acc[mt][0], al[0], al[1], al[2], al[3], Bh[0][kf][0], Bh[0][kf][1]);
                mma_bf16(acc[mt][1], al[0], al[1], al[2], al[3], Bh[1][kf][0], Bh[1][kf][1]);
            }
        }

        // ---- epilogue: relu + W2 partial dot (b1/W2 from smem) ----
        #pragma unroll
        for (int mt = 0; mt < 4; mt++) {
            float p0 = 0.f, p1 = 0.f;
            #pragma unroll
            for (int nt = 0; nt < 2; nt++) {
                int n0 = warpN + nt * 8 + tig * 2;
                float bb0 = b1s[n0], bb1 = b1s[n0 + 1];
                float ww0 = W2s[n0], ww1 = W2s[n0 + 1];
                p0 = fmaf(fmaxf(acc[mt][nt][0] + bb0, 0.f), ww0, p0);
                p0 = fmaf(fmaxf(acc[mt][nt][1] + bb1, 0.f), ww1, p0);
                p1 = fmaf(fmaxf(acc[mt][nt][2] + bb0, 0.f), ww0, p1);
                p1 = fmaf(fmaxf(acc[mt][nt][3] + bb1, 0.f), ww1, p1);
            }
            p0 += __shfl_xor_sync(0xFFFFFFFFu, p0, 1);
            p0 += __shfl_xor_sync(0xFFFFFFFFu, p0, 2);
            p1 += __shfl_xor_sync(0xFFFFFFFFu, p1, 1);
            p1 += __shfl_xor_sync(0xFFFFFFFFu, p1, 2);
            if (tig == 0) {
                part[(mt * 16 + g) * 9 + wid] = p0;
                part[(mt * 16 + g + 8) * 9 + wid] = p1;
            }
        }
        __syncthreads();

        if (tid < TROWS) {
            float s = b2[0];
            #pragma unroll
            for (int w = 0; w < 8; w++) s += part[tid * 9 + w];
            int op = base + tid;
            if (op < N) {
                d_scores[op] = s;
                if (s > tBest || (s == tBest && op < tArg)) { tBest = s; tArg = op; }
            }
        }
        __syncthreads();
    }

    // block argmax (approx scores)
    float* rv = (float*)smem;
    int*   ri = (int*)(smem + 1024);
    rv[tid] = tBest; ri[tid] = tArg;
    __syncthreads();
    for (int s = 128; s > 0; s >>= 1) {
        if (tid < s) {
            float v = rv[tid + s]; int ix = ri[tid + s];
            if (v > rv[tid] || (v == rv[tid] && ix < ri[tid])) { rv[tid] = v; ri[tid] = ix; }
        }
        __syncthreads();
    }
    if (tid == 0) { d_bMax[blockIdx.x] = rv[0]; d_bArg[blockIdx.x] = ri[0]; }
}

// ---------------- reductions ----------------
__global__ void red_max2(int nparts) {
    __shared__ float sv[256];
    __shared__ int   si[256];
    float best = -3.402823466e38f;
    int bidx = 0x7FFFFFFF;
    for (int i = threadIdx.x; i < nparts; i += 256) {
        float v = d_bMax[i]; int ix = d_bArg[i];
        if (v > best || (v == best && ix < bidx)) { best = v; bidx = ix; }
    }
    sv[threadIdx.x] = best; si[threadIdx.x] = bidx;
    __syncthreads();
    for (int s = 128; s > 0; s >>= 1) {
        if (threadIdx.x < s) {
            float v = sv[threadIdx.x + s]; int ix = si[threadIdx.x + s];
            if (v > sv[threadIdx.x] || (v == sv[threadIdx.x] && ix < si[threadIdx.x])) {
                sv[threadIdx.x] = v; si[threadIdx.x] = ix;
            }
        }
        __syncthreads();
    }
    if (threadIdx.x == 0) { d_gMax = sv[0]; d_gArg = si[0]; d_candCount = 0; }
}

// one pass: entropy partial sums + candidate collection
__global__ void red_sum_scan(int N) {
    __shared__ float sE[256];
    __shared__ float sS[256];
    float mx = d_gMax;
    float thr = mx - 1e-3f;
    float se = 0.f, ss = 0.f;
    for (int i = blockIdx.x * 256 + threadIdx.x; i < N; i += gridDim.x * 256) {
        float v = d_scores[i];
        float t = v - mx;
        float e = expf(t);
        se += e;
        ss = fmaf(t, e, ss);
        if (v >= thr) {
            int p = atomicAdd(&d_candCount, 1);
            if (p < CANDCAP) d_candList[p] = i;
        }
    }
    sE[threadIdx.x] = se; sS[threadIdx.x] = ss;
    __syncthreads();
    for (int s = 128; s > 0; s >>= 1) {
        if (threadIdx.x < s) {
            sE[threadIdx.x] += sE[threadIdx.x + s];
            sS[threadIdx.x] += sS[threadIdx.x + s];
        }
        __syncthreads();
    }
    if (threadIdx.x == 0) { d_pSumE[blockIdx.x] = sE[0]; d_pSumS[blockIdx.x] = sS[0]; }
}

// exact fp32 rescoring of candidates, deterministic winner
__global__ void refine_kernel(const int* __restrict__ m_ids,
                              const int* __restrict__ job_idx,
                              const float* __restrict__ W1,
                              const float* __restrict__ b1,
                              const float* __restrict__ W2,
                              const float* __restrict__ b2) {
    __shared__ float h0[128];
    __shared__ float red[128];
    __shared__ float bestS;
    __shared__ int bestI;
    int tid = threadIdx.x;
    if (tid == 0) { bestS = -3.402823466e38f; bestI = 0x7FFFFFFF; }
    int cnt = d_candCount;
    if (cnt > CANDCAP) cnt = CANDCAP;
    __syncthreads();
    for (int c = 0; c < cnt; c++) {
        int op = d_candList[c];
        int m = m_ids[op], j = job_idx[op];
        h0[tid] = fmaxf(d_Qm[m * HDIM + tid] + d_Pj[j * HDIM + tid], 0.f);
        __syncthreads();
        float a = b1[tid];
        #pragma unroll 8
        for (int k = 0; k < HDIM; k++)
            a = fmaf(h0[k], W1[k * HDIM + tid], a);
        red[tid] = fmaxf(a, 0.f) * W2[tid];
        __syncthreads();
        for (int s = 64; s > 0; s >>= 1) {
            if (tid < s) red[tid] += red[tid + s];
            __syncthreads();
        }
        if (tid == 0) {
            float s = red[0] + b2[0];
            if (s > bestS || (s == bestS && op < bestI)) { bestS = s; bestI = op; }
        }
        __syncthreads();
    }
    if (tid == 0) d_exArg = bestI;
}

__global__ void finalize_kernel(float* __restrict__ out) {
    __shared__ float sE[256];
    __shared__ float sS[256];
    sE[threadIdx.x] = d_pSumE[threadIdx.x];
    sS[threadIdx.x] = d_pSumS[threadIdx.x];
    __syncthreads();
    for (int s = 128; s > 0; s >>= 1) {
        if (threadIdx.x < s) {
            sE[threadIdx.x] += sE[threadIdx.x + s];
            sS[threadIdx.x] += sS[threadIdx.x + s];
        }
        __syncthreads();
    }
    if (threadIdx.x == 0) {
        float Z = sE[0], S = sS[0];
        float mx = d_gMax;
        int arg = d_exArg;
        float logZ = logf(Z);
        float lp = (d_scores[arg] - mx) - logZ;
        out[0] = (float)arg;
        out[1] = expf(lp);
        out[2] = lp;
        out[3] = logZ - S / Z;
    }
}

// ---------------- launch ----------------
extern "C" void kernel_launch(void* const* d_in, const int* in_sizes, int n_in,
                              void* d_out, int out_size) {
    const float* xg    = (const float*)d_in[0];
    const float* xm    = (const float*)d_in[1];
    const float* xjob  = (const float*)d_in[2];
    const int*   m_ids = (const int*)d_in[3];
    const int*   jidx  = (const int*)d_in[4];
    const float* W0    = (const float*)d_in[5];
    const float* b0    = (const float*)d_in[6];
    const float* W1    = (const float*)d_in[7];
    const float* b1    = (const float*)d_in[8];
    const float* W2    = (const float*)d_in[9];
    const float* b2    = (const float*)d_in[10];

    int M = in_sizes[1] / HDIM;
    int J = in_sizes[2] / HDIM;
    int N = in_sizes[3];

    const int SMEM_PRE = (16384 + 4096) * 4;
    cudaFuncSetAttribute(pre_kernel, cudaFuncAttributeMaxDynamicSharedMemorySize, SMEM_PRE);
    cudaFuncSetAttribute(mma_main,   cudaFuncAttributeMaxDynamicSharedMemorySize, SMEM_MMA);

    g0_kernel<<<1, 128>>>(xg, W0, b0);

    int gQm = (M + 31) / 32;
    int gPj = (J + 31) / 32;
    pre_kernel<<<gQm, 256, SMEM_PRE>>>(xm,   W0 + 256 * HDIM, M, 0);
    pre_kernel<<<gPj, 256, SMEM_PRE>>>(xjob, W0 + 384 * HDIM, J, 1);

    const int GRID_MAIN = 304;
    mma_main<<<GRID_MAIN, 256, SMEM_MMA>>>(m_ids, jidx, W1, b1, W2, b2, N);

    red_max2<<<1, 256>>>(GRID_MAIN);
    red_sum_scan<<<RBLOCKS, 256>>>(N);
    refine_kernel<<<1, 128>>>(m_ids, jidx, W1, b1, W2, b2);
    finalize_kernel<<<1, 256>>>((float*)d_out);
}

// round 8
// speedup vs baseline: 1.6066x; 1.0190x over previous
#include <cuda_runtime.h>
#include <cuda_bf16.h>
#include <cstdint>

#define HDIM 128
#define RBLOCKS 256
#define MAXGRID 512
#define CANDCAP 1024

// ---------------- device scratch (static, no allocation) ----------------
__device__ float d_G0[HDIM];
__device__ float d_Qm[1000 * HDIM];
__device__ float d_Pj[5000 * HDIM];
__device__ float d_scores[200000];
__device__ float d_bMax[MAXGRID];
__device__ int   d_bArg[MAXGRID];
__device__ float d_gMax;
__device__ int   d_gArg;
__device__ int   d_candCount;
__device__ int   d_candList[CANDCAP];
__device__ int   d_exArg;
__device__ float d_pSumE[RBLOCKS];
__device__ float d_pSumS[RBLOCKS];

// ---------------- k0 ----------------
__global__ void g0_kernel(const float* __restrict__ xg,
                          const float* __restrict__ W0,
                          const float* __restrict__ b0) {
    int k = threadIdx.x;
    __shared__ float xs[2 * HDIM];
    xs[k] = xg[k];
    xs[k + HDIM] = xg[k + HDIM];
    __syncthreads();
    float acc = b0[k];
    #pragma unroll 8
    for (int c = 0; c < 2 * HDIM; c++)
        acc = fmaf(xs[c], W0[c * HDIM + k], acc);
    d_G0[k] = acc;
}

// ---------------- k1: Out[r,:] = X[r,:] @ Wp (+ G0 if mode==0) ----------------
__global__ void pre_kernel(const float* __restrict__ X,
                           const float* __restrict__ Wp,
                           int rows, int mode) {
    extern __shared__ float sm[];
    float* Ws = sm;
    float* Xs = sm + 16384;
    int tid = threadIdx.x;
    {
        const float4* Wg = (const float4*)Wp;
        float4* Ws4 = (float4*)Ws;
        for (int i = tid; i < 4096; i += 256) Ws4[i] = Wg[i];
    }
    __syncthreads();
    int og = tid >> 5, cg = tid & 31;
    float addv[4];
    #pragma unroll
    for (int u = 0; u < 4; u++) addv[u] = (mode == 0) ? d_G0[cg * 4 + u] : 0.0f;
    float* Out = (mode == 0) ? d_Qm : d_Pj;
    int ntiles = (rows + 31) >> 5;
    for (int tile = blockIdx.x; tile < ntiles; tile += gridDim.x) {
        int base = tile << 5;
        for (int s = tid; s < 1024; s += 256) {
            int r = s >> 5, c4 = (s & 31) << 2;
            float4 v = make_float4(0.f, 0.f, 0.f, 0.f);
            if (base + r < rows) v = *(const float4*)&X[(base + r) * HDIM + c4];
            *(float4*)&Xs[r * HDIM + c4] = v;
        }
        __syncthreads();
        float acc[4][4];
        #pragma unroll
        for (int o = 0; o < 4; o++)
            #pragma unroll
            for (int u = 0; u < 4; u++) acc[o][u] = 0.0f;
        #pragma unroll 4
        for (int c = 0; c < HDIM; c += 4) {
            float4 a[4];
            #pragma unroll
            for (int o = 0; o < 4; o++) a[o] = *(float4*)&Xs[(og * 4 + o) * HDIM + c];
            #pragma unroll
            for (int u = 0; u < 4; u++) {
                float4 w = *(float4*)&Ws[(c + u) * HDIM + cg * 4];
                #pragma unroll
                for (int o = 0; o < 4; o++) {
                    float av = (&a[o].x)[u];
                    acc[o][0] = fmaf(av, w.x, acc[o][0]);
                    acc[o][1] = fmaf(av, w.y, acc[o][1]);
                    acc[o][2] = fmaf(av, w.z, acc[o][2]);
                    acc[o][3] = fmaf(av, w.w, acc[o][3]);
                }
            }
        }
        #pragma unroll
        for (int o = 0; o < 4; o++) {
            int r = base + og * 4 + o;
            if (r < rows) {
                float4 v;
                v.x = acc[o][0] + addv[0]; v.y = acc[o][1] + addv[1];
                v.z = acc[o][2] + addv[2]; v.w = acc[o][3] + addv[3];
                *(float4*)&Out[r * HDIM + cg * 4] = v;
            }
        }
        __syncthreads();
    }
}

// ============ HMMA main kernel: 32-row tiles, warps = 4 N-groups x 2 K-groups ============
#define TROWS 32
#define RS 136                              // padded A row stride (elems), 272B
#define A_HALF_BYTES (TROWS * RS * 2)       // 8704
#define OFF_AL   A_HALF_BYTES
#define OFF_KX   (2 * A_HALF_BYTES)         // 17408 ; kx: 4 ng x [32][33] floats
#define KXNG     (32 * 33)
#define OFF_B1S  (OFF_KX + 4 * KXNG * 4)    // 34304
#define OFF_W2S  (OFF_B1S + 512)
#define OFF_PART (OFF_W2S + 512)            // [32][5] floats
#define SMEM_MMA (OFF_PART + 32 * 5 * 4)

__device__ __forceinline__ void mma_bf16(float* d, uint32_t a0, uint32_t a1,
                                         uint32_t a2, uint32_t a3,
                                         uint32_t b0, uint32_t b1) {
    asm volatile(
        "mma.sync.aligned.m16n8k16.row.col.f32.bf16.bf16.f32 "
        "{%0,%1,%2,%3}, {%4,%5,%6,%7}, {%8,%9}, {%0,%1,%2,%3};"
        : "+f"(d[0]), "+f"(d[1]), "+f"(d[2]), "+f"(d[3])
        : "r"(a0), "r"(a1), "r"(a2), "r"(a3), "r"(b0), "r"(b1));
}

__device__ __forceinline__ void ldsm_x4(uint32_t* r, uint32_t saddr) {
    asm volatile("ldmatrix.sync.aligned.m8n8.x4.shared.b16 {%0,%1,%2,%3}, [%4];"
        : "=r"(r[0]), "=r"(r[1]), "=r"(r[2]), "=r"(r[3]) : "r"(saddr));
}

__device__ __forceinline__ uint32_t smem_u32(const void* p) {
    uint32_t a;
    asm("{ .reg .u64 t; cvta.to.shared.u64 t, %1; cvt.u32.u64 %0, t; }" : "=r"(a) : "l"(p));
    return a;
}

__device__ __forceinline__ uint32_t pack_bf16x2(__nv_bfloat16 lo, __nv_bfloat16 hi) {
    __nv_bfloat162 p(lo, hi);
    return *(uint32_t*)&p;
}

__global__ void __launch_bounds__(256, 2)
mma_main(const int* __restrict__ m_ids,
         const int* __restrict__ job_idx,
         const float* __restrict__ W1,
         const float* __restrict__ b1,
         const float* __restrict__ W2,
         const float* __restrict__ b2,
         int N) {
    extern __shared__ char smem[];
    __nv_bfloat16* Ah = (__nv_bfloat16*)smem;
    float* kx   = (float*)(smem + OFF_KX);
    float* b1s  = (float*)(smem + OFF_B1S);
    float* W2s  = (float*)(smem + OFF_W2S);
    float* part = (float*)(smem + OFF_PART);

    int tid = threadIdx.x;
    int wid = tid >> 5;
    int lane = tid & 31;
    int g = lane >> 2;        // 0..7
    int tig = lane & 3;       // 0..3
    int ng = wid & 3;         // N group: cols ng*32..+31
    int kg = wid >> 2;        // K group: kf = kg*4..kg*4+3

    if (tid < HDIM) { b1s[tid] = b1[tid]; W2s[tid] = W2[tid]; }

    // ---- persistent B fragments: 32 N-cols x 64 K-cols per warp (hi/lo) ----
    uint32_t Bh[4][4][2], Bl[4][4][2];
    #pragma unroll
    for (int nt = 0; nt < 4; nt++) {
        int n = ng * 32 + nt * 8 + g;
        #pragma unroll
        for (int kfi = 0; kfi < 4; kfi++) {
            #pragma unroll
            for (int r = 0; r < 2; r++) {
                int k0 = (kg * 4 + kfi) * 16 + r * 8 + tig * 2;
                float w0 = W1[k0 * HDIM + n];
                float w1 = W1[(k0 + 1) * HDIM + n];
                __nv_bfloat16 h0 = __float2bfloat16_rn(w0);
                __nv_bfloat16 h1 = __float2bfloat16_rn(w1);
                Bh[nt][kfi][r] = pack_bf16x2(h0, h1);
                Bl[nt][kfi][r] = pack_bf16x2(
                    __float2bfloat16_rn(w0 - __bfloat162float(h0)),
                    __float2bfloat16_rn(w1 - __bfloat162float(h1)));
            }
        }
    }

    uint32_t AhS = smem_u32(Ah);
    uint32_t laneByte = (uint32_t)(((lane & 15) * RS + (lane >> 4) * 8) * 2);
    uint32_t AhLane = AhS + laneByte + (uint32_t)(kg * 64 * 2);   // kg's K half
    uint32_t AlLane = AhLane + OFF_AL;

    float tBest = -3.402823466e38f;
    int   tArg  = 0x7FFFFFFF;

    int ntiles = (N + TROWS - 1) / TROWS;
    for (int tile = blockIdx.x; tile < ntiles; tile += gridDim.x) {
        int base = tile * TROWS;

        // ---- gather: h0 = relu(Qm[m]+Pj[j]) -> bf16 hi/lo padded SMEM ----
        {
            int row = tid >> 3;          // 0..31
            int oct = tid & 7;           // cols oct*16..+15
            int op = base + row;
            bool valid = (op < N);
            int m = valid ? m_ids[op] : 0;
            int j = valid ? job_idx[op] : 0;
            const float4* q4 = (const float4*)&d_Qm[m * HDIM + oct * 16];
            const float4* p4 = (const float4*)&d_Pj[j * HDIM + oct * 16];
            int ebase = row * RS + oct * 16;
            #pragma unroll
            for (int it = 0; it < 4; it++) {
                float4 q = q4[it], p = p4[it];
                float h0 = valid ? fmaxf(q.x + p.x, 0.f) : 0.f;
                float h1 = valid ? fmaxf(q.y + p.y, 0.f) : 0.f;
                float h2 = valid ? fmaxf(q.z + p.z, 0.f) : 0.f;
                float h3 = valid ? fmaxf(q.w + p.w, 0.f) : 0.f;
                __nv_bfloat16 a0 = __float2bfloat16_rn(h0);
                __nv_bfloat16 a1 = __float2bfloat16_rn(h1);
                __nv_bfloat16 a2 = __float2bfloat16_rn(h2);
                __nv_bfloat16 a3 = __float2bfloat16_rn(h3);
                uint2 hv, lv;
                hv.x = pack_bf16x2(a0, a1);
                hv.y = pack_bf16x2(a2, a3);
                lv.x = pack_bf16x2(__float2bfloat16_rn(h0 - __bfloat162float(a0)),
                                   __float2bfloat16_rn(h1 - __bfloat162float(a1)));
                lv.y = pack_bf16x2(__float2bfloat16_rn(h2 - __bfloat162float(a2)),
                                   __float2bfloat16_rn(h3 - __bfloat162float(a3)));
                *(uint2*)&Ah[ebase + it * 4] = hv;
                *(uint2*)((char*)&Ah[ebase + it * 4] + OFF_AL) = lv;
            }
        }
        __syncthreads();

        // ---- MMA over this warp's K half: acc += Ah*Bh + Ah*Bl + Al*Bh ----
        float acc[2][4][4];
        #pragma unroll
        for (int mt = 0; mt < 2; mt++)
            #pragma unroll
            for (int nt = 0; nt < 4; nt++)
                #pragma unroll
                for (int e = 0; e < 4; e++) acc[mt][nt][e] = 0.f;

        #pragma unroll
        for (int kfi = 0; kfi < 4; kfi++) {
            uint32_t kOff = (uint32_t)(kfi * 32);
            #pragma unroll
            for (int mt = 0; mt < 2; mt++) {
                uint32_t rOff = (uint32_t)(mt * 16 * RS * 2) + kOff;
                uint32_t ah[4], al[4];
                ldsm_x4(ah, AhLane + rOff);
                ldsm_x4(al, AlLane + rOff);
                #pragma unroll
                for (int nt = 0; nt < 4; nt++) {
                    mma_bf16(acc[mt][nt], ah[0], ah[1], ah[2], ah[3], Bh[nt][kfi][0], Bh[nt][kfi][1]);
                    mma_bf16(acc[mt][nt], ah[0], ah[1], ah[2], ah[3], Bl[nt][kfi][0], Bl[nt][kfi][1]);
                    mma_bf16(acc[mt][nt], al[0], al[1], al[2], al[3], Bh[nt][kfi][0], Bh[nt][kfi][1]);
                }
            }
        }

        // ---- K exchange: kg1 stores partials, kg0 adds ----
        if (kg == 1) {
            float* kxb = kx + ng * KXNG;
            #pragma unroll
            for (int mt = 0; mt < 2; mt++)
                #pragma unroll
                for (int nt = 0; nt < 4; nt++)
                    #pragma unroll
                    for (int e = 0; e < 4; e++) {
                        int row = mt * 16 + g + (e >> 1) * 8;
                        int col = nt * 8 + tig * 2 + (e & 1);
                        kxb[row * 33 + col] = acc[mt][nt][e];
                    }
        }
        __syncthreads();
        if (kg == 0) {
            float* kxb = kx + ng * KXNG;
            #pragma unroll
            for (int mt = 0; mt < 2; mt++) {
                float p0 = 0.f, p1 = 0.f;
                #pragma unroll
                for (int nt = 0; nt < 4; nt++) {
                    int n0 = ng * 32 + nt * 8 + tig * 2;
                    float bb0 = b1s[n0], bb1 = b1s[n0 + 1];
                    float ww0 = W2s[n0], ww1 = W2s[n0 + 1];
                    int r0 = mt * 16 + g, r1 = r0 + 8;
                    int c0 = nt * 8 + tig * 2;
                    float v0 = acc[mt][nt][0] + kxb[r0 * 33 + c0];
                    float v1 = acc[mt][nt][1] + kxb[r0 * 33 + c0 + 1];
                    float v2 = acc[mt][nt][2] + kxb[r1 * 33 + c0];
                    float v3 = acc[mt][nt][3] + kxb[r1 * 33 + c0 + 1];
                    p0 = fmaf(fmaxf(v0 + bb0, 0.f), ww0, p0);
                    p0 = fmaf(fmaxf(v1 + bb1, 0.f), ww1, p0);
                    p1 = fmaf(fmaxf(v2 + bb0, 0.f), ww0, p1);
                    p1 = fmaf(fmaxf(v3 + bb1, 0.f), ww1, p1);
                }
                p0 += __shfl_xor_sync(0xFFFFFFFFu, p0, 1);
                p0 += __shfl_xor_sync(0xFFFFFFFFu, p0, 2);
                p1 += __shfl_xor_sync(0xFFFFFFFFu, p1, 1);
                p1 += __shfl_xor_sync(0xFFFFFFFFu, p1, 2);
                if (tig == 0) {
                    part[(mt * 16 + g) * 5 + ng] = p0;
                    part[(mt * 16 + g + 8) * 5 + ng] = p1;
                }
            }
        }
        __syncthreads();

        if (tid < TROWS) {
            float s = b2[0] + part[tid * 5] + part[tid * 5 + 1]
                    + part[tid * 5 + 2] + part[tid * 5 + 3];
            int op = base + tid;
            if (op < N) {
                d_scores[op] = s;
                if (s > tBest || (s == tBest && op < tArg)) { tBest = s; tArg = op; }
            }
        }
        __syncthreads();
    }

    // block argmax (approx scores)
    float* rv = (float*)smem;
    int*   ri = (int*)(smem + 1024);
    rv[tid] = tBest; ri[tid] = tArg;
    __syncthreads();
    for (int s = 128; s > 0; s >>= 1) {
        if (tid < s) {
            float v = rv[tid + s]; int ix = ri[tid + s];
            if (v > rv[tid] || (v == rv[tid] && ix < ri[tid])) { rv[tid] = v; ri[tid] = ix; }
        }
        __syncthreads();
    }
    if (tid == 0) { d_bMax[blockIdx.x] = rv[0]; d_bArg[blockIdx.x] = ri[0]; }
}

// ---------------- reductions ----------------
__global__ void red_max2(int nparts) {
    __shared__ float sv[256];
    __shared__ int   si[256];
    float best = -3.402823466e38f;
    int bidx = 0x7FFFFFFF;
    for (int i = threadIdx.x; i < nparts; i += 256) {
        float v = d_bMax[i]; int ix = d_bArg[i];
        if (v > best || (v == best && ix < bidx)) { best = v; bidx = ix; }
    }
    sv[threadIdx.x] = best; si[threadIdx.x] = bidx;
    __syncthreads();
    for (int s = 128; s > 0; s >>= 1) {
        if (threadIdx.x < s) {
            float v = sv[threadIdx.x + s]; int ix = si[threadIdx.x + s];
            if (v > sv[threadIdx.x] || (v == sv[threadIdx.x] && ix < si[threadIdx.x])) {
                sv[threadIdx.x] = v; si[threadIdx.x] = ix;
            }
        }
        __syncthreads();
    }
    if (threadIdx.x == 0) { d_gMax = sv[0]; d_gArg = si[0]; d_candCount = 0; }
}

// one pass: entropy partial sums + candidate collection
__global__ void red_sum_scan(int N) {
    __shared__ float sE[256];
    __shared__ float sS[256];
    float mx = d_gMax;
    float thr = mx - 1e-3f;
    float se = 0.f, ss = 0.f;
    for (int i = blockIdx.x * 256 + threadIdx.x; i < N; i += gridDim.x * 256) {
        float v = d_scores[i];
        float t = v - mx;
        float e = expf(t);
        se += e;
        ss = fmaf(t, e, ss);
        if (v >= thr) {
            int p = atomicAdd(&d_candCount, 1);
            if (p < CANDCAP) d_candList[p] = i;
        }
    }
    sE[threadIdx.x] = se; sS[threadIdx.x] = ss;
    __syncthreads();
    for (int s = 128; s > 0; s >>= 1) {
        if (threadIdx.x < s) {
            sE[threadIdx.x] += sE[threadIdx.x + s];
            sS[threadIdx.x] += sS[threadIdx.x + s];
        }
        __syncthreads();
    }
    if (threadIdx.x == 0) { d_pSumE[blockIdx.x] = sE[0]; d_pSumS[blockIdx.x] = sS[0]; }
}

// exact fp32 rescoring of candidates, deterministic winner
__global__ void refine_kernel(const int* __restrict__ m_ids,
                              const int* __restrict__ job_idx,
                              const float* __restrict__ W1,
                              const float* __restrict__ b1,
                              const float* __restrict__ W2,
                              const float* __restrict__ b2) {
    __shared__ float h0[128];
    __shared__ float red[128];
    __shared__ float bestS;
    __shared__ int bestI;
    int tid = threadIdx.x;
    if (tid == 0) { bestS = -3.402823466e38f; bestI = 0x7FFFFFFF; }
    int cnt = d_candCount;
    if (cnt > CANDCAP) cnt = CANDCAP;
    __syncthreads();
    for (int c = 0; c < cnt; c++) {
        int op = d_candList[c];
        int m = m_ids[op], j = job_idx[op];
        h0[tid] = fmaxf(d_Qm[m * HDIM + tid] + d_Pj[j * HDIM + tid], 0.f);
        __syncthreads();
        float a = b1[tid];
        #pragma unroll 8
        for (int k = 0; k < HDIM; k++)
            a = fmaf(h0[k], W1[k * HDIM + tid], a);
        red[tid] = fmaxf(a, 0.f) * W2[tid];
        __syncthreads();
        for (int s = 64; s > 0; s >>= 1) {
            if (tid < s) red[tid] += red[tid + s];
            __syncthreads();
        }
        if (tid == 0) {
            float s = red[0] + b2[0];
            if (s > bestS || (s == bestS && op < bestI)) { bestS = s; bestI = op; }
        }
        __syncthreads();
    }
    if (tid == 0) d_exArg = bestI;
}

__global__ void finalize_kernel(float* __restrict__ out) {
    __shared__ float sE[256];
    __shared__ float sS[256];
    sE[threadIdx.x] = d_pSumE[threadIdx.x];
    sS[threadIdx.x] = d_pSumS[threadIdx.x];
    __syncthreads();
    for (int s = 128; s > 0; s >>= 1) {
        if (threadIdx.x < s) {
            sE[threadIdx.x] += sE[threadIdx.x + s];
            sS[threadIdx.x] += sS[threadIdx.x + s];
        }
        __syncthreads();
    }
    if (threadIdx.x == 0) {
        float Z = sE[0], S = sS[0];
        float mx = d_gMax;
        int arg = d_exArg;
        float logZ = logf(Z);
        float lp = (d_scores[arg] - mx) - logZ;
        out[0] = (float)arg;
        out[1] = expf(lp);
        out[2] = lp;
        out[3] = logZ - S / Z;
    }
}

// ---------------- launch ----------------
extern "C" void kernel_launch(void* const* d_in, const int* in_sizes, int n_in,
                              void* d_out, int out_size) {
    const float* xg    = (const float*)d_in[0];
    const float* xm    = (const float*)d_in[1];
    const float* xjob  = (const float*)d_in[2];
    const int*   m_ids = (const int*)d_in[3];
    const int*   jidx  = (const int*)d_in[4];
    const float* W0    = (const float*)d_in[5];
    const float* b0    = (const float*)d_in[6];
    const float* W1    = (const float*)d_in[7];
    const float* b1    = (const float*)d_in[8];
    const float* W2    = (const float*)d_in[9];
    const float* b2    = (const float*)d_in[10];

    int M = in_sizes[1] / HDIM;
    int J = in_sizes[2] / HDIM;
    int N = in_sizes[3];

    const int SMEM_PRE = (16384 + 4096) * 4;
    cudaFuncSetAttribute(pre_kernel, cudaFuncAttributeMaxDynamicSharedMemorySize, SMEM_PRE);
    cudaFuncSetAttribute(mma_main,   cudaFuncAttributeMaxDynamicSharedMemorySize, SMEM_MMA);

    g0_kernel<<<1, 128>>>(xg, W0, b0);

    int gQm = (M + 31) / 32;
    int gPj = (J + 31) / 32;
    pre_kernel<<<gQm, 256, SMEM_PRE>>>(xm,   W0 + 256 * HDIM, M, 0);
    pre_kernel<<<gPj, 256, SMEM_PRE>>>(xjob, W0 + 384 * HDIM, J, 1);

    const int GRID_MAIN = 304;
    mma_main<<<GRID_MAIN, 256, SMEM_MMA>>>(m_ids, jidx, W1, b1, W2, b2, N);

    red_max2<<<1, 256>>>(GRID_MAIN);
    red_sum_scan<<<RBLOCKS, 256>>>(N);
    refine_kernel<<<1, 128>>>(m_ids, jidx, W1, b1, W2, b2);
    finalize_kernel<<<1, 256>>>((float*)d_out);
}

// round 10
// speedup vs baseline: 1.9701x; 1.2262x over previous
#include <cuda_runtime.h>
#include <cuda_bf16.h>
#include <cstdint>

#define HDIM 128
#define RBLOCKS 256
#define MAXGRID 512
#define CANDCAP 1024

// ---------------- device scratch (static, no allocation) ----------------
__device__ float d_Qm[1000 * HDIM];
__device__ float d_Pj[5000 * HDIM];
__device__ float d_scores[200000];
__device__ float d_bMax[MAXGRID];
__device__ int   d_bArg[MAXGRID];
__device__ float d_gMax;
__device__ int   d_gArg;
__device__ int   d_candCount;
__device__ int   d_candList[CANDCAP];
__device__ float d_pSumE[RBLOCKS];
__device__ float d_pSumS[RBLOCKS];

// ---------------- fused pre kernel: Qm (with G0) and Pj ----------------
__global__ void pre_kernel(const float* __restrict__ Xm,
                           const float* __restrict__ Xj,
                           const float* __restrict__ W0,
                           const float* __restrict__ b0,
                           const float* __restrict__ xg,
                           int M, int J, int gQm) {
    extern __shared__ float sm[];
    float* Ws = sm;
    float* Xs = sm + 16384;
    float* G0 = sm + 16384 + 4096;
    int tid = threadIdx.x;

    int mode = (blockIdx.x < gQm) ? 0 : 1;
    int tile = (mode == 0) ? blockIdx.x : blockIdx.x - gQm;
    int rows = (mode == 0) ? M : J;
    const float* X  = (mode == 0) ? Xm : Xj;
    const float* Wp = W0 + ((mode == 0) ? 256 : 384) * HDIM;
    float* Out = (mode == 0) ? d_Qm : d_Pj;

    {
        const float4* Wg = (const float4*)Wp;
        float4* Ws4 = (float4*)Ws;
        for (int i = tid; i < 4096; i += 256) Ws4[i] = Wg[i];
    }
    if (mode == 0 && tid < HDIM) {
        float acc = b0[tid];
        #pragma unroll 8
        for (int c = 0; c < 2 * HDIM; c++)
            acc = fmaf(xg[c], W0[c * HDIM + tid], acc);
        G0[tid] = acc;
    }
    __syncthreads();

    int og = tid >> 5, cg = tid & 31;
    float addv[4];
    #pragma unroll
    for (int u = 0; u < 4; u++)
        addv[u] = (mode == 0) ? G0[cg * 4 + u] : 0.0f;

    int base = tile << 5;
    for (int s = tid; s < 1024; s += 256) {
        int r = s >> 5, c4 = (s & 31) << 2;
        float4 v = make_float4(0.f, 0.f, 0.f, 0.f);
        if (base + r < rows) v = *(const float4*)&X[(base + r) * HDIM + c4];
        *(float4*)&Xs[r * HDIM + c4] = v;
    }
    __syncthreads();
    float acc[4][4];
    #pragma unroll
    for (int o = 0; o < 4; o++)
        #pragma unroll
        for (int u = 0; u < 4; u++) acc[o][u] = 0.0f;
    #pragma unroll 4
    for (int c = 0; c < HDIM; c += 4) {
        float4 a[4];
        #pragma unroll
        for (int o = 0; o < 4; o++) a[o] = *(float4*)&Xs[(og * 4 + o) * HDIM + c];
        #pragma unroll
        for (int u = 0; u < 4; u++) {
            float4 w = *(float4*)&Ws[(c + u) * HDIM + cg * 4];
            #pragma unroll
            for (int o = 0; o < 4; o++) {
                float av = (&a[o].x)[u];
                acc[o][0] = fmaf(av, w.x, acc[o][0]);
                acc[o][1] = fmaf(av, w.y, acc[o][1]);
                acc[o][2] = fmaf(av, w.z, acc[o][2]);
                acc[o][3] = fmaf(av, w.w, acc[o][3]);
            }
        }
    }
    #pragma unroll
    for (int o = 0; o < 4; o++) {
        int r = base + og * 4 + o;
        if (r < rows) {
            float4 v;
            v.x = acc[o][0] + addv[0]; v.y = acc[o][1] + addv[1];
            v.z = acc[o][2] + addv[2]; v.w = acc[o][3] + addv[3];
            *(float4*)&Out[r * HDIM + cg * 4] = v;
        }
    }
}

// ============ HMMA main: 32-row tiles, cp.async pipelined ============
#define TROWS 32
#define RS 136
#define RAWBUF  32768
#define OFF_AH  (2 * RAWBUF)
#define OFF_AL  (OFF_AH + TROWS * RS * 2)
#define OFF_KX  (OFF_AL + TROWS * RS * 2)
#define KXNG    (32 * 33)
#define OFF_B1S (OFF_KX + 4 * KXNG * 4)
#define OFF_W2S (OFF_B1S + 512)
#define OFF_IDX (OFF_W2S + 512)
#define SMEM_MMA (OFF_IDX + 512 + 256)

__device__ __forceinline__ void mma_bf16(float* d, uint32_t a0, uint32_t a1,
                                         uint32_t a2, uint32_t a3,
                                         uint32_t b0, uint32_t b1) {
    asm volatile(
        "mma.sync.aligned.m16n8k16.row.col.f32.bf16.bf16.f32 "
        "{%0,%1,%2,%3}, {%4,%5,%6,%7}, {%8,%9}, {%0,%1,%2,%3};"
        : "+f"(d[0]), "+f"(d[1]), "+f"(d[2]), "+f"(d[3])
        : "r"(a0), "r"(a1), "r"(a2), "r"(a3), "r"(b0), "r"(b1));
}
__device__ __forceinline__ void ldsm_x4(uint32_t* r, uint32_t saddr) {
    asm volatile("ldmatrix.sync.aligned.m8n8.x4.shared.b16 {%0,%1,%2,%3}, [%4];"
        : "=r"(r[0]), "=r"(r[1]), "=r"(r[2]), "=r"(r[3]) : "r"(saddr));
}
__device__ __forceinline__ uint32_t smem_u32(const void* p) {
    uint32_t a;
    asm("{ .reg .u64 t; cvta.to.shared.u64 t, %1; cvt.u32.u64 %0, t; }" : "=r"(a) : "l"(p));
    return a;
}
__device__ __forceinline__ uint32_t pack_bf16x2(__nv_bfloat16 lo, __nv_bfloat16 hi) {
    __nv_bfloat162 p(lo, hi);
    return *(uint32_t*)&p;
}
__device__ __forceinline__ void cp16(uint32_t dst, const void* src) {
    asm volatile("cp.async.cg.shared.global [%0], [%1], 16;" :: "r"(dst), "l"(src));
}
#define CP_COMMIT() asm volatile("cp.async.commit_group;" ::: "memory")
#define CP_WAIT0()  asm volatile("cp.async.wait_group 0;" ::: "memory")

__global__ void __launch_bounds__(256, 2)
mma_main(const int* __restrict__ m_ids,
         const int* __restrict__ job_idx,
         const float* __restrict__ W1,
         const float* __restrict__ b1,
         const float* __restrict__ W2,
         const float* __restrict__ b2,
         int N) {
    extern __shared__ char smem[];
    uint32_t smemB = smem_u32(smem);
    float* kx   = (float*)(smem + OFF_KX);
    float* b1s  = (float*)(smem + OFF_B1S);
    float* W2s  = (float*)(smem + OFF_W2S);

    int tid = threadIdx.x;
    int wid = tid >> 5;
    int lane = tid & 31;
    int g = lane >> 2;
    int tig = lane & 3;
    int ng = wid & 3;
    int kg = wid >> 2;

    if (tid < HDIM) { b1s[tid] = b1[tid]; W2s[tid] = W2[tid]; }

    uint32_t Bh[4][4][2], Bl[4][4][2];
    #pragma unroll
    for (int nt = 0; nt < 4; nt++) {
        int n = ng * 32 + nt * 8 + g;
        #pragma unroll
        for (int kfi = 0; kfi < 4; kfi++) {
            #pragma unroll
            for (int r = 0; r < 2; r++) {
                int k0 = (kg * 4 + kfi) * 16 + r * 8 + tig * 2;
                float w0 = W1[k0 * HDIM + n];
                float w1 = W1[(k0 + 1) * HDIM + n];
                __nv_bfloat16 h0 = __float2bfloat16_rn(w0);
                __nv_bfloat16 h1 = __float2bfloat16_rn(w1);
                Bh[nt][kfi][r] = pack_bf16x2(h0, h1);
                Bl[nt][kfi][r] = pack_bf16x2(
                    __float2bfloat16_rn(w0 - __bfloat162float(h0)),
                    __float2bfloat16_rn(w1 - __bfloat162float(h1)));
            }
        }
    }

    uint32_t laneByte = (uint32_t)(((lane & 15) * RS + (lane >> 4) * 8) * 2);
    uint32_t AhLane = smemB + OFF_AH + laneByte + (uint32_t)(kg * 64 * 2);
    uint32_t AlLane = smemB + OFF_AL + laneByte + (uint32_t)(kg * 64 * 2);

    int ntiles = (N + TROWS - 1) / TROWS;
    int stride = gridDim.x;

    float tBest = -3.402823466e38f;
    int   tArg  = 0x7FFFFFFF;

    #pragma unroll
    for (int s = 0; s < 2; s++) {
        int ts = blockIdx.x + s * stride;
        if (tid < 64 && ts < ntiles) {
            int r = tid & 31;
            int op = ts * TROWS + r; if (op >= N) op = N - 1;
            int v = (tid < 32) ? m_ids[op] : job_idx[op];
            *((int*)(smem + OFF_IDX + s * 256) + ((tid < 32) ? 0 : 32) + r) = v;
        }
    }
    __syncthreads();
    if (blockIdx.x < ntiles) {
        int* im = (int*)(smem + OFF_IDX);
        int* ij = im + 32;
        #pragma unroll
        for (int k = 0; k < 4; k++) {
            int chunk = tid + k * 256;
            int row = chunk >> 5, seg = chunk & 31;
            cp16(smemB + row * 512 + seg * 16, d_Qm + im[row] * HDIM + seg * 4);
            cp16(smemB + 16384 + row * 512 + seg * 16, d_Pj + ij[row] * HDIM + seg * 4);
        }
    }
    CP_COMMIT();

    int i = 0;
    for (int tile = blockIdx.x; tile < ntiles; i++, tile += stride) {
        int b = i & 1;
        int rawOff = b * RAWBUF;

        CP_WAIT0();
        __syncthreads();

        {
            float* rq = (float*)(smem + rawOff);
            float* rp = (float*)(smem + rawOff + 16384);
            __nv_bfloat16* Ahp = (__nv_bfloat16*)(smem + OFF_AH);
            #pragma unroll
            for (int it = 0; it < 4; it++) {
                int row = wid * 4 + it;
                float4 q = *(float4*)&rq[row * 128 + lane * 4];
                float4 p = *(float4*)&rp[row * 128 + lane * 4];
                float h0 = fmaxf(q.x + p.x, 0.f);
                float h1 = fmaxf(q.y + p.y, 0.f);
                float h2 = fmaxf(q.z + p.z, 0.f);
                float h3 = fmaxf(q.w + p.w, 0.f);
                __nv_bfloat16 a0 = __float2bfloat16_rn(h0);
                __nv_bfloat16 a1 = __float2bfloat16_rn(h1);
                __nv_bfloat16 a2 = __float2bfloat16_rn(h2);
                __nv_bfloat16 a3 = __float2bfloat16_rn(h3);
                uint2 hv, lv;
                hv.x = pack_bf16x2(a0, a1);
                hv.y = pack_bf16x2(a2, a3);
                lv.x = pack_bf16x2(__float2bfloat16_rn(h0 - __bfloat162float(a0)),
                                   __float2bfloat16_rn(h1 - __bfloat162float(a1)));
                lv.y = pack_bf16x2(__float2bfloat16_rn(h2 - __bfloat162float(a2)),
                                   __float2bfloat16_rn(h3 - __bfloat162float(a3)));
                *(uint2*)&Ahp[row * RS + lane * 4] = hv;
                *(uint2*)((char*)&Ahp[row * RS + lane * 4] + (OFF_AL - OFF_AH)) = lv;
            }
        }
        int pfv = 0;
        int t2 = tile + 2 * stride;
        bool hp = (t2 < ntiles) && (tid < 64);
        if (hp) {
            int r = tid & 31;
            int op = t2 * TROWS + r; if (op >= N) op = N - 1;
            pfv = (tid < 32) ? m_ids[op] : job_idx[op];
        }
        __syncthreads();

        if (tile + stride < ntiles) {
            int slot1 = (i + 1) & 1;
            int* im = (int*)(smem + OFF_IDX + slot1 * 256);
            int* ij = im + 32;
            uint32_t dstQ = smemB + (b ^ 1) * RAWBUF;
            #pragma unroll
            for (int k = 0; k < 4; k++) {
                int chunk = tid + k * 256;
                int row = chunk >> 5, seg = chunk & 31;
                cp16(dstQ + row * 512 + seg * 16, d_Qm + im[row] * HDIM + seg * 4);
                cp16(dstQ + 16384 + row * 512 + seg * 16, d_Pj + ij[row] * HDIM + seg * 4);
            }
        }
        CP_COMMIT();
        if (hp) {
            int r = tid & 31;
            *((int*)(smem + OFF_IDX + (i & 1) * 256) + ((tid < 32) ? 0 : 32) + r) = pfv;
        }

        float acc[2][4][4];
        #pragma unroll
        for (int mt = 0; mt < 2; mt++)
            #pragma unroll
            for (int nt = 0; nt < 4; nt++)
                #pragma unroll
                for (int e = 0; e < 4; e++) acc[mt][nt][e] = 0.f;

        #pragma unroll
        for (int kfi = 0; kfi < 4; kfi++) {
            uint32_t kOff = (uint32_t)(kfi * 32);
            #pragma unroll
            for (int mt = 0; mt < 2; mt++) {
                uint32_t rOff = (uint32_t)(mt * 16 * RS * 2) + kOff;
                uint32_t ah[4], al[4];
                ldsm_x4(ah, AhLane + rOff);
                ldsm_x4(al, AlLane + rOff);
                #pragma unroll
                for (int nt = 0; nt < 4; nt++) {
                    mma_bf16(acc[mt][nt], ah[0], ah[1], ah[2], ah[3], Bh[nt][kfi][0], Bh[nt][kfi][1]);
                    mma_bf16(acc[mt][nt], ah[0], ah[1], ah[2], ah[3], Bl[nt][kfi][0], Bl[nt][kfi][1]);
                    mma_bf16(acc[mt][nt], al[0], al[1], al[2], al[3], Bh[nt][kfi][0], Bh[nt][kfi][1]);
                }
            }
        }

        if (kg == 1) {
            float* kxb = kx + ng * KXNG;
            #pragma unroll
            for (int mt = 0; mt < 2; mt++)
                #pragma unroll
                for (int nt = 0; nt < 4; nt++)
                    #pragma unroll
                    for (int e = 0; e < 4; e++) {
                        int row = mt * 16 + g + (e >> 1) * 8;
                        int col = nt * 8 + tig * 2 + (e & 1);
                        kxb[row * 33 + col] = acc[mt][nt][e];
                    }
        }
        __syncthreads();
        if (kg == 0) {
            float* kxb = kx + ng * KXNG;
            #pragma unroll
            for (int mt = 0; mt < 2; mt++) {
                float p0 = 0.f, p1 = 0.f;
                #pragma unroll
                for (int nt = 0; nt < 4; nt++) {
                    int n0 = ng * 32 + nt * 8 + tig * 2;
                    float bb0 = b1s[n0], bb1 = b1s[n0 + 1];
                    float ww0 = W2s[n0], ww1 = W2s[n0 + 1];
                    int r0 = mt * 16 + g, r1 = r0 + 8;
                    int c0 = nt * 8 + tig * 2;
                    float v0 = acc[mt][nt][0] + kxb[r0 * 33 + c0];
                    float v1 = acc[mt][nt][1] + kxb[r0 * 33 + c0 + 1];
                    float v2 = acc[mt][nt][2] + kxb[r1 * 33 + c0];
                    float v3 = acc[mt][nt][3] + kxb[r1 * 33 + c0 + 1];
                    p0 = fmaf(fmaxf(v0 + bb0, 0.f), ww0, p0);
                    p0 = fmaf(fmaxf(v1 + bb1, 0.f), ww1, p0);
                    p1 = fmaf(fmaxf(v2 + bb0, 0.f), ww0, p1);
                    p1 = fmaf(fmaxf(v3 + bb1, 0.f), ww1, p1);
                }
                p0 += __shfl_xor_sync(0xFFFFFFFFu, p0, 1);
                p0 += __shfl_xor_sync(0xFFFFFFFFu, p0, 2);
                p1 += __shfl_xor_sync(0xFFFFFFFFu, p1, 1);
                p1 += __shfl_xor_sync(0xFFFFFFFFu, p1, 2);
                if (tig == 0) {
                    kxb[(mt * 16 + g) * 33 + 32] = p0;
                    kxb[(mt * 16 + g + 8) * 33 + 32] = p1;
                }
            }
        }
        __syncthreads();

        if (tid < TROWS) {
            float s = b2[0];
            #pragma unroll
            for (int n4 = 0; n4 < 4; n4++) s += kx[n4 * KXNG + tid * 33 + 32];
            int op = tile * TROWS + tid;
            if (op < N) {
                d_scores[op] = s;
                if (s > tBest || (s == tBest && op < tArg)) { tBest = s; tArg = op; }
            }
        }
        __syncthreads();
    }

    float* rv = (float*)smem;
    int*   ri = (int*)(smem + 1024);
    rv[tid] = tBest; ri[tid] = tArg;
    __syncthreads();
    for (int s = 128; s > 0; s >>= 1) {
        if (tid < s) {
            float v = rv[tid + s]; int ix = ri[tid + s];
            if (v > rv[tid] || (v == rv[tid] && ix < ri[tid])) { rv[tid] = v; ri[tid] = ix; }
        }
        __syncthreads();
    }
    if (tid == 0) { d_bMax[blockIdx.x] = rv[0]; d_bArg[blockIdx.x] = ri[0]; }
}

// ---------------- reductions ----------------
__global__ void red_max2(int nparts) {
    __shared__ float sv[256];
    __shared__ int   si[256];
    float best = -3.402823466e38f;
    int bidx = 0x7FFFFFFF;
    for (int i = threadIdx.x; i < nparts; i += 256) {
        float v = d_bMax[i]; int ix = d_bArg[i];
        if (v > best || (v == best && ix < bidx)) { best = v; bidx = ix; }
    }
    sv[threadIdx.x] = best; si[threadIdx.x] = bidx;
    __syncthreads();
    for (int s = 128; s > 0; s >>= 1) {
        if (threadIdx.x < s) {
            float v = sv[threadIdx.x + s]; int ix = si[threadIdx.x + s];
            if (v > sv[threadIdx.x] || (v == sv[threadIdx.x] && ix < si[threadIdx.x])) {
                sv[threadIdx.x] = v; si[threadIdx.x] = ix;
            }
        }
        __syncthreads();
    }
    if (threadIdx.x == 0) { d_gMax = sv[0]; d_gArg = si[0]; d_candCount = 0; }
}

__global__ void red_sum_scan(int N) {
    __shared__ float sE[256];
    __shared__ float sS[256];
    float mx = d_gMax;
    float thr = mx - 1e-3f;
    float se = 0.f, ss = 0.f;
    for (int i = blockIdx.x * 256 + threadIdx.x; i < N; i += gridDim.x * 256) {
        float v = d_scores[i];
        float t = v - mx;
        float e = expf(t);
        se += e;
        ss = fmaf(t, e, ss);
        if (v >= thr) {
            int p = atomicAdd(&d_candCount, 1);
            if (p < CANDCAP) d_candList[p] = i;
        }
    }
    sE[threadIdx.x] = se; sS[threadIdx.x] = ss;
    __syncthreads();
    for (int s = 128; s > 0; s >>= 1) {
        if (threadIdx.x < s) {
            sE[threadIdx.x] += sE[threadIdx.x + s];
            sS[threadIdx.x] += sS[threadIdx.x + s];
        }
        __syncthreads();
    }
    if (threadIdx.x == 0) { d_pSumE[blockIdx.x] = sE[0]; d_pSumS[blockIdx.x] = sS[0]; }
}

__global__ void refine_finalize(const int* __restrict__ m_ids,
                                const int* __restrict__ job_idx,
                                const float* __restrict__ W1,
                                const float* __restrict__ b1,
                                const float* __restrict__ W2,
                                const float* __restrict__ b2,
                                float* __restrict__ out) {
    __shared__ float h0[128];
    __shared__ float red[128];
    __shared__ float bestS;
    __shared__ int bestI;
    int tid = threadIdx.x;
    if (tid == 0) { bestS = -3.402823466e38f; bestI = 0x7FFFFFFF; }
    int cnt = d_candCount;
    if (cnt > CANDCAP) cnt = CANDCAP;
    __syncthreads();
    for (int c = 0; c < cnt; c++) {
        int op = d_candList[c];
        int m = m_ids[op], j = job_idx[op];
        h0[tid] = fmaxf(d_Qm[m * HDIM + tid] + d_Pj[j * HDIM + tid], 0.f);
        __syncthreads();
        float a = b1[tid];
        #pragma unroll 8
        for (int k = 0; k < HDIM; k++)
            a = fmaf(h0[k], W1[k * HDIM + tid], a);
        red[tid] = fmaxf(a, 0.f) * W2[tid];
        __syncthreads();
        for (int s = 64; s > 0; s >>= 1) {
            if (tid < s) red[tid] += red[tid + s];
            __syncthreads();
        }
        if (tid == 0) {
            float s = red[0] + b2[0];
            if (s > bestS || (s == bestS && op < bestI)) { bestS = s; bestI = op; }
        }
        __syncthreads();
    }
    red[tid] = d_pSumE[tid] + d_pSumE[tid + 128];
    h0[tid]  = d_pSumS[tid] + d_pSumS[tid + 128];
    __syncthreads();
    for (int s = 64; s > 0; s >>= 1) {
        if (tid < s) { red[tid] += red[tid + s]; h0[tid] += h0[tid + s]; }
        __syncthreads();
    }
    if (tid == 0) {
        float Z = red[0], S = h0[0];
        float mx = d_gMax;
        int arg = bestI;
        float logZ = logf(Z);
        float lp = (d_scores[arg] - mx) - logZ;
        out[0] = (float)arg;
        out[1] = expf(lp);
        out[2] = lp;
        out[3] = logZ - S / Z;
    }
}

// ---------------- launch ----------------
extern "C" void kernel_launch(void* const* d_in, const int* in_sizes, int n_in,
                              void* d_out, int out_size) {
    const float* xg    = (const float*)d_in[0];
    const float* xm    = (const float*)d_in[1];
    const float* xjob  = (const float*)d_in[2];
    const int*   m_ids = (const int*)d_in[3];
    const int*   jidx  = (const int*)d_in[4];
    const float* W0    = (const float*)d_in[5];
    const float* b0    = (const float*)d_in[6];
    const float* W1    = (const float*)d_in[7];
    const float* b1    = (const float*)d_in[8];
    const float* W2    = (const float*)d_in[9];
    const float* b2    = (const float*)d_in[10];

    int M = in_sizes[1] / HDIM;
    int J = in_sizes[2] / HDIM;
    int N = in_sizes[3];

    const int SMEM_PRE = (16384 + 4096 + 128) * 4;
    cudaFuncSetAttribute(pre_kernel, cudaFuncAttributeMaxDynamicSharedMemorySize, SMEM_PRE);
    cudaFuncSetAttribute(mma_main,   cudaFuncAttributeMaxDynamicSharedMemorySize, SMEM_MMA);

    int gQm = (M + 31) / 32;
    int gPj = (J + 31) / 32;
    pre_kernel<<<gQm + gPj, 256, SMEM_PRE>>>(xm, xjob, W0, b0, xg, M, J, gQm);

    const int GRID_MAIN = 304;
    mma_main<<<GRID_MAIN, 256, SMEM_MMA>>>(m_ids, jidx, W1, b1, W2, b2, N);

    red_max2<<<1, 256>>>(GRID_MAIN);
    red_sum_scan<<<RBLOCKS, 256>>>(N);
    refine_finalize<<<1, 128>>>(m_ids, jidx, W1, b1, W2, b2, (float*)d_out);
}